// round 2
// baseline (speedup 1.0000x reference)
#include <cuda_runtime.h>
#include <cuda_bf16.h>
#include <cstdint>

typedef unsigned long long ull;

// ---------------- packed f32x2 helpers (B300 FFMA2 path) ----------------
__device__ __forceinline__ ull pk2(float lo, float hi) {
    ull r; asm("mov.b64 %0, {%1, %2};" : "=l"(r) : "f"(lo), "f"(hi)); return r;
}
__device__ __forceinline__ void upk2(ull v, float& lo, float& hi) {
    asm("mov.b64 {%0, %1}, %2;" : "=f"(lo), "=f"(hi) : "l"(v));
}
__device__ __forceinline__ void ffma2(ull& d, ull a, ull b) {
    asm("fma.rn.f32x2 %0, %1, %2, %0;" : "+l"(d) : "l"(a), "l"(b));
}
__device__ __forceinline__ ull fmul2(ull a, ull b) {
    ull d; asm("mul.rn.f32x2 %0, %1, %2;" : "=l"(d) : "l"(a), "l"(b)); return d;
}

// ---------------- scratch (allocation-free rule: device globals) --------
__device__ float g_qkv[(size_t)16384 * 3072];  // 192 MB  qkv activations
__device__ float g_att[(size_t)16384 * 1024];  //  64 MB  attention output

// ======================= GEMM: C = A @ B + bias ==========================
// A [M,K] row-major, B [K,N] row-major, bias [N]. M%128==0, N%128==0, K%16==0.
template<int BM, int BN, int BK>
__global__ void __launch_bounds__(256)
gemm_bias_kernel(const float* __restrict__ A, const float* __restrict__ B,
                 const float* __restrict__ bias, float* __restrict__ C,
                 int M, int N, int K)
{
    __shared__ float As[BK][BM + 4];   // stored [k][m], pad 4 -> stride 132
    __shared__ float Bs[BK][BN + 4];   // stored [k][n]

    const int tid = threadIdx.x;
    const int tx = tid & 15;           // 0..15  (N direction)
    const int ty = tid >> 4;           // 0..15  (M direction)
    const int m0 = blockIdx.y * BM;
    const int n0 = blockIdx.x * BN;

    const int aRow  = tid >> 2;        // 0..63
    const int aCol4 = (tid & 3) * 4;   // 0,4,8,12
    const int bRow  = tid >> 5;        // 0..7
    const int bCol4 = (tid & 31) * 4;  // 0..124

    ull acc[8][4];
    #pragma unroll
    for (int i = 0; i < 8; i++)
        #pragma unroll
        for (int j = 0; j < 4; j++) acc[i][j] = pk2(0.f, 0.f);

    for (int k0 = 0; k0 < K; k0 += BK) {
        // load A tile 128x16, store transposed
        #pragma unroll
        for (int r = 0; r < 2; r++) {
            float4 v = *(const float4*)&A[(size_t)(m0 + aRow + 64 * r) * K + k0 + aCol4];
            As[aCol4 + 0][aRow + 64 * r] = v.x;
            As[aCol4 + 1][aRow + 64 * r] = v.y;
            As[aCol4 + 2][aRow + 64 * r] = v.z;
            As[aCol4 + 3][aRow + 64 * r] = v.w;
        }
        // load B tile 16x128
        #pragma unroll
        for (int r = 0; r < 2; r++) {
            float4 v = *(const float4*)&B[(size_t)(k0 + bRow + 8 * r) * N + n0 + bCol4];
            *(float4*)&Bs[bRow + 8 * r][bCol4] = v;
        }
        __syncthreads();

        #pragma unroll
        for (int kk = 0; kk < BK; kk++) {
            float4 a0 = *(const float4*)&As[kk][ty * 8];
            float4 a1 = *(const float4*)&As[kk][ty * 8 + 4];
            float4 b0 = *(const float4*)&Bs[kk][tx * 4];
            float4 b1 = *(const float4*)&Bs[kk][64 + tx * 4];
            ull bp[4] = { pk2(b0.x, b0.y), pk2(b0.z, b0.w),
                          pk2(b1.x, b1.y), pk2(b1.z, b1.w) };
            float av[8] = { a0.x, a0.y, a0.z, a0.w, a1.x, a1.y, a1.z, a1.w };
            #pragma unroll
            for (int i = 0; i < 8; i++) {
                ull ap = pk2(av[i], av[i]);
                #pragma unroll
                for (int j = 0; j < 4; j++) ffma2(acc[i][j], ap, bp[j]);
            }
        }
        __syncthreads();
    }

    // epilogue: columns are split {n0+tx*4 .. +3} and {n0+64+tx*4 .. +3}
    const int c0 = n0 + tx * 4;
    const int c1 = n0 + 64 + tx * 4;
    float4 bia0 = *(const float4*)&bias[c0];
    float4 bia1 = *(const float4*)&bias[c1];
    #pragma unroll
    for (int i = 0; i < 8; i++) {
        size_t row = (size_t)(m0 + ty * 8 + i);
        float o0, o1, o2, o3, o4, o5, o6, o7;
        upk2(acc[i][0], o0, o1); upk2(acc[i][1], o2, o3);
        upk2(acc[i][2], o4, o5); upk2(acc[i][3], o6, o7);
        float4 w0 = make_float4(o0 + bia0.x, o1 + bia0.y, o2 + bia0.z, o3 + bia0.w);
        float4 w1 = make_float4(o4 + bia1.x, o5 + bia1.y, o6 + bia1.z, o7 + bia1.w);
        *(float4*)&C[row * N + c0] = w0;
        *(float4*)&C[row * N + c1] = w1;
    }
}

// ======================= blocked ring attention ==========================
// grid: 4096 CTAs = (b:2, h:16, blk:16, qt:8); 256 threads.
// Each CTA: 64 q-rows, two flash passes (local block, next block), outputs summed.
__global__ void __launch_bounds__(256)
attn_kernel(const float* __restrict__ qkv, float* __restrict__ att)
{
    extern __shared__ float sm[];
    float* Qs = sm;                   // [64 d][68]  (transposed: Qs[d*68 + q]), pre-scaled
    float* Ks = Qs + 64 * 68;         // [64 k][65]  Ks[k*65 + d]
    float* Vs = Ks + 64 * 65;         // [64 k][68]  Vs[k*68 + d]
    float* Ps = Vs + 64 * 68;         // [64 q][68]  Ps[q*68 + k]

    const int tid    = threadIdx.x;
    const int lane16 = tid & 15;
    const int g16    = tid >> 4;      // 0..15
    const int q0     = g16 * 4;       // this thread's 4 q-rows

    const int cta = blockIdx.x;
    const int qt  = cta & 7;
    const int blk = (cta >> 3) & 15;
    const int h   = (cta >> 7) & 15;
    const int b   = cta >> 11;

    const size_t rowbase = (size_t)b * 8192;
    const int s0   = blk * 512 + qt * 64;
    const int colQ = h * 64;
    const int colK = 1024 + h * 64;
    const int colV = 2048 + h * 64;

    // ---- load Q tile (64x64), fold in scale, store transposed ----
    {
        const float scale = 0.125f;   // 1/sqrt(64)
        #pragma unroll
        for (int it = 0; it < 4; it++) {
            int r  = g16 + 16 * it;
            int d4 = lane16 * 4;
            float4 v = *(const float4*)&qkv[(rowbase + s0 + r) * 3072 + colQ + d4];
            Qs[(d4 + 0) * 68 + r] = v.x * scale;
            Qs[(d4 + 1) * 68 + r] = v.y * scale;
            Qs[(d4 + 2) * 68 + r] = v.z * scale;
            Qs[(d4 + 3) * 68 + r] = v.w * scale;
        }
    }

    // ---- K/V chunk register prefetch ----
    float4 kreg[4], vreg[4];
    auto load_chunk = [&](int c) {
        int pass = c >> 3;
        int kb   = pass ? ((blk + 1) & 15) : blk;
        int srow = kb * 512 + (c & 7) * 64;
        #pragma unroll
        for (int it = 0; it < 4; it++) {
            int r  = g16 + 16 * it;
            int d4 = lane16 * 4;
            size_t base = (rowbase + srow + r) * 3072;
            kreg[it] = *(const float4*)&qkv[base + colK + d4];
            vreg[it] = *(const float4*)&qkv[base + colV + d4];
        }
    };
    load_chunk(0);

    float m[4], l[4], ofin[4][4];
    ull oacc[4][2];
    #pragma unroll
    for (int i = 0; i < 4; i++) {
        m[i] = -1e30f; l[i] = 0.f;
        oacc[i][0] = oacc[i][1] = pk2(0.f, 0.f);
        #pragma unroll
        for (int j = 0; j < 4; j++) ofin[i][j] = 0.f;
    }

    for (int c = 0; c < 16; c++) {
        __syncthreads();   // previous chunk's consumers done
        // commit prefetched K/V to smem
        #pragma unroll
        for (int it = 0; it < 4; it++) {
            int r  = g16 + 16 * it;
            int d4 = lane16 * 4;
            Ks[r * 65 + d4 + 0] = kreg[it].x;
            Ks[r * 65 + d4 + 1] = kreg[it].y;
            Ks[r * 65 + d4 + 2] = kreg[it].z;
            Ks[r * 65 + d4 + 3] = kreg[it].w;
            *(float4*)&Vs[r * 68 + d4] = vreg[it];
        }
        if (c < 15) load_chunk(c + 1);   // hide gmem latency behind compute
        __syncthreads();

        // ---- S = Q @ K^T : s[i][j] over keys k_j = lane16 + 16*j ----
        ull sacc[4][2];
        #pragma unroll
        for (int i = 0; i < 4; i++) { sacc[i][0] = sacc[i][1] = pk2(0.f, 0.f); }
        #pragma unroll 16
        for (int d = 0; d < 64; d++) {
            float4 qv = *(const float4*)&Qs[d * 68 + q0];
            float k0v = Ks[(lane16     ) * 65 + d];
            float k1v = Ks[(lane16 + 16) * 65 + d];
            float k2v = Ks[(lane16 + 32) * 65 + d];
            float k3v = Ks[(lane16 + 48) * 65 + d];
            ull kp01 = pk2(k0v, k1v), kp23 = pk2(k2v, k3v);
            ull q0p = pk2(qv.x, qv.x), q1p = pk2(qv.y, qv.y);
            ull q2p = pk2(qv.z, qv.z), q3p = pk2(qv.w, qv.w);
            ffma2(sacc[0][0], q0p, kp01); ffma2(sacc[0][1], q0p, kp23);
            ffma2(sacc[1][0], q1p, kp01); ffma2(sacc[1][1], q1p, kp23);
            ffma2(sacc[2][0], q2p, kp01); ffma2(sacc[2][1], q2p, kp23);
            ffma2(sacc[3][0], q3p, kp01); ffma2(sacc[3][1], q3p, kp23);
        }

        // ---- online softmax (rows live in 16-lane groups) ----
        #pragma unroll
        for (int i = 0; i < 4; i++) {
            float sv0, sv1, sv2, sv3;
            upk2(sacc[i][0], sv0, sv1);
            upk2(sacc[i][1], sv2, sv3);
            float cm = fmaxf(fmaxf(sv0, sv1), fmaxf(sv2, sv3));
            #pragma unroll
            for (int w = 8; w >= 1; w >>= 1)
                cm = fmaxf(cm, __shfl_xor_sync(0xffffffffu, cm, w));
            float mn    = fmaxf(m[i], cm);
            float alpha = __expf(m[i] - mn);
            float p0 = __expf(sv0 - mn), p1 = __expf(sv1 - mn);
            float p2 = __expf(sv2 - mn), p3 = __expf(sv3 - mn);
            float rs = p0 + p1 + p2 + p3;
            #pragma unroll
            for (int w = 8; w >= 1; w >>= 1)
                rs += __shfl_xor_sync(0xffffffffu, rs, w);
            l[i] = l[i] * alpha + rs;
            m[i] = mn;
            ull am = pk2(alpha, alpha);
            oacc[i][0] = fmul2(oacc[i][0], am);
            oacc[i][1] = fmul2(oacc[i][1], am);
            Ps[(q0 + i) * 68 + lane16     ] = p0;
            Ps[(q0 + i) * 68 + lane16 + 16] = p1;
            Ps[(q0 + i) * 68 + lane16 + 32] = p2;
            Ps[(q0 + i) * 68 + lane16 + 48] = p3;
        }
        __syncthreads();

        // ---- O += P @ V : this thread owns dims d0..d0+3 ----
        {
            const int d0 = lane16 * 4;
            #pragma unroll 16
            for (int k = 0; k < 64; k++) {
                float4 vv = *(const float4*)&Vs[k * 68 + d0];
                ull vp0 = pk2(vv.x, vv.y), vp1 = pk2(vv.z, vv.w);
                #pragma unroll
                for (int i = 0; i < 4; i++) {
                    float pv = Ps[(q0 + i) * 68 + k];
                    ull pp = pk2(pv, pv);
                    ffma2(oacc[i][0], pp, vp0);
                    ffma2(oacc[i][1], pp, vp1);
                }
            }
        }

        // ---- end of a pass: normalize, accumulate, reset ----
        if ((c & 7) == 7) {
            #pragma unroll
            for (int i = 0; i < 4; i++) {
                float inv = 1.0f / l[i];
                float o0, o1, o2, o3;
                upk2(oacc[i][0], o0, o1);
                upk2(oacc[i][1], o2, o3);
                ofin[i][0] += o0 * inv; ofin[i][1] += o1 * inv;
                ofin[i][2] += o2 * inv; ofin[i][3] += o3 * inv;
                m[i] = -1e30f; l[i] = 0.f;
                oacc[i][0] = oacc[i][1] = pk2(0.f, 0.f);
            }
        }
    }

    // ---- write out: att[b, s, h*64 + d] ----
    {
        const int d0 = lane16 * 4;
        #pragma unroll
        for (int i = 0; i < 4; i++) {
            float4 w = make_float4(ofin[i][0], ofin[i][1], ofin[i][2], ofin[i][3]);
            *(float4*)&att[(rowbase + s0 + q0 + i) * 1024 + h * 64 + d0] = w;
        }
    }
}

// ============================ launcher ===================================
extern "C" void kernel_launch(void* const* d_in, const int* in_sizes, int n_in,
                              void* d_out, int out_size)
{
    const float* x    = (const float*)d_in[0];
    const float* Wqkv = (const float*)d_in[1];
    const float* bqkv = (const float*)d_in[2];
    const float* Wout = (const float*)d_in[3];
    const float* bout = (const float*)d_in[4];
    float* out = (float*)d_out;

    float* qkv; cudaGetSymbolAddress((void**)&qkv, g_qkv);
    float* att; cudaGetSymbolAddress((void**)&att, g_att);

    const int attn_smem = (64 * 68 + 64 * 65 + 64 * 68 + 64 * 68) * 4;  // 68864 B
    cudaFuncSetAttribute(attn_kernel, cudaFuncAttributeMaxDynamicSharedMemorySize,
                         attn_smem);

    // 1) qkv = x @ W_qkv + b_qkv        [16384,1024]x[1024,3072]
    gemm_bias_kernel<128, 128, 16><<<dim3(3072 / 128, 16384 / 128), 256>>>(
        x, Wqkv, bqkv, qkv, 16384, 3072, 1024);

    // 2) blocked ring attention -> att  [16384,1024]
    attn_kernel<<<4096, 256, attn_smem>>>(qkv, att);

    // 3) out = att @ W_out + b_out      [16384,1024]x[1024,1024]
    gemm_bias_kernel<128, 128, 16><<<dim3(1024 / 128, 16384 / 128), 256>>>(
        att, Wout, bout, out, 16384, 1024, 1024);
}

// round 4
// speedup vs baseline: 1.3436x; 1.3436x over previous
#include <cuda_runtime.h>
#include <cuda_bf16.h>
#include <cstdint>

typedef unsigned long long ull;

// ===================== PTX helpers (baseline, compute_103-safe) ==========
__device__ __forceinline__ uint32_t smem_u32(const void* p) {
    uint32_t a;
    asm("{ .reg .u64 t; cvta.to.shared.u64 t, %1; cvt.u32.u64 %0, t; }"
        : "=r"(a) : "l"(p));
    return a;
}
__device__ __forceinline__ void cp_async16(uint32_t dst, const void* src) {
    asm volatile("cp.async.cg.shared.global [%0], [%1], 16;" :: "r"(dst), "l"(src));
}
#define CP_COMMIT() asm volatile("cp.async.commit_group;" ::: "memory")
template <int N>
__device__ __forceinline__ void cp_wait() {
    asm volatile("cp.async.wait_group %0;" :: "n"(N) : "memory");
}
__device__ __forceinline__ uint32_t lds32(uint32_t a) {
    uint32_t v;
    asm volatile("ld.shared.b32 %0, [%1];" : "=r"(v) : "r"(a));
    return v;
}
// mma.sync m16n8k16 row.col bf16 -> f32 (sm_80+ baseline feature)
__device__ __forceinline__ void mma16816(float* d, const uint32_t* a, const uint32_t* b) {
    asm volatile(
        "mma.sync.aligned.m16n8k16.row.col.f32.bf16.bf16.f32 "
        "{%0,%1,%2,%3}, {%4,%5,%6,%7}, {%8,%9}, {%0,%1,%2,%3};"
        : "+f"(d[0]), "+f"(d[1]), "+f"(d[2]), "+f"(d[3])
        : "r"(a[0]), "r"(a[1]), "r"(a[2]), "r"(a[3]), "r"(b[0]), "r"(b[1]));
}

// ---------------- packed f32x2 helpers (attention kernel) ----------------
__device__ __forceinline__ ull pk2(float lo, float hi) {
    ull r; asm("mov.b64 %0, {%1, %2};" : "=l"(r) : "f"(lo), "f"(hi)); return r;
}
__device__ __forceinline__ void upk2(ull v, float& lo, float& hi) {
    asm("mov.b64 {%0, %1}, %2;" : "=f"(lo), "=f"(hi) : "l"(v));
}
__device__ __forceinline__ void ffma2(ull& d, ull a, ull b) {
    asm("fma.rn.f32x2 %0, %1, %2, %0;" : "+l"(d) : "l"(a), "l"(b));
}
__device__ __forceinline__ ull fmul2(ull a, ull b) {
    ull d; asm("mul.rn.f32x2 %0, %1, %2;" : "=l"(d) : "l"(a), "l"(b)); return d;
}

// ---------------- scratch (allocation-free rule: device globals) --------
__device__ float g_qkv[(size_t)16384 * 3072];          // 192 MB
__device__ float g_att[(size_t)16384 * 1024];          //  64 MB
__device__ __nv_bfloat16 g_xhi[(size_t)16384 * 1024];
__device__ __nv_bfloat16 g_xlo[(size_t)16384 * 1024];
__device__ __nv_bfloat16 g_whi[(size_t)3072 * 1024];   // W_qkv^T split
__device__ __nv_bfloat16 g_wlo[(size_t)3072 * 1024];
__device__ __nv_bfloat16 g_ahi[(size_t)16384 * 1024];
__device__ __nv_bfloat16 g_alo[(size_t)16384 * 1024];
__device__ __nv_bfloat16 g_ohi[(size_t)1024 * 1024];   // W_out^T split
__device__ __nv_bfloat16 g_olo[(size_t)1024 * 1024];

// ===================== conversion kernels =====================
__global__ void __launch_bounds__(256)
split_kernel(const float* __restrict__ src, __nv_bfloat16* __restrict__ hi,
             __nv_bfloat16* __restrict__ lo)
{
    size_t i = ((size_t)blockIdx.x * 256 + threadIdx.x) * 4;
    float4 v = *(const float4*)(src + i);
    __nv_bfloat162* hp = (__nv_bfloat162*)(hi + i);
    __nv_bfloat162* lp = (__nv_bfloat162*)(lo + i);
    __nv_bfloat16 h0 = __float2bfloat16(v.x), h1 = __float2bfloat16(v.y);
    __nv_bfloat16 h2 = __float2bfloat16(v.z), h3 = __float2bfloat16(v.w);
    hp[0] = __nv_bfloat162(h0, h1);
    hp[1] = __nv_bfloat162(h2, h3);
    lp[0] = __nv_bfloat162(__float2bfloat16(v.x - __bfloat162float(h0)),
                           __float2bfloat16(v.y - __bfloat162float(h1)));
    lp[1] = __nv_bfloat162(__float2bfloat16(v.z - __bfloat162float(h2)),
                           __float2bfloat16(v.w - __bfloat162float(h3)));
}

// W [K,N] fp32 -> W^T [N,K] bf16 hi/lo
__global__ void __launch_bounds__(256)
transpose_split_kernel(const float* __restrict__ W, __nv_bfloat16* __restrict__ hiT,
                       __nv_bfloat16* __restrict__ loT, int K, int N)
{
    __shared__ float t[32][33];
    int n0 = blockIdx.x * 32, k0 = blockIdx.y * 32;
    int tx = threadIdx.x, ty = threadIdx.y;
    #pragma unroll
    for (int i = 0; i < 4; i++)
        t[ty + 8 * i][tx] = W[(size_t)(k0 + ty + 8 * i) * N + n0 + tx];
    __syncthreads();
    #pragma unroll
    for (int i = 0; i < 4; i++) {
        float v = t[tx][ty + 8 * i];
        __nv_bfloat16 h = __float2bfloat16(v);
        size_t o = (size_t)(n0 + ty + 8 * i) * K + k0 + tx;
        hiT[o] = h;
        loT[o] = __float2bfloat16(v - __bfloat162float(h));
    }
}

// ===================== HMMA bf16x3 GEMM =====================
// C[M,N] = (Ahi+Alo)[M,1024] x ((Bhi+Blo)[N,1024])^T + bias, fp32 out.
// tile 128x128, K chunks of 32 bf16, 3-stage cp.async pipeline.
// smem per operand tile: 128 rows x 80 bytes (32 bf16 + pad to 40) = 10240 B.
#define OP_BYTES   10240u
#define STG_BYTES  40960u   // 4 operands per stage

__global__ void __launch_bounds__(256)
gemm_hmma_kernel(const __nv_bfloat16* __restrict__ Ahi, const __nv_bfloat16* __restrict__ Alo,
                 const __nv_bfloat16* __restrict__ Bhi, const __nv_bfloat16* __restrict__ Blo,
                 const float* __restrict__ bias, float* __restrict__ C, int N)
{
    extern __shared__ __align__(16) char dsm[];
    const int tid  = threadIdx.x;
    const int wid  = tid >> 5;
    const int lane = tid & 31;
    const int g    = lane >> 2;     // 0..7
    const int tig  = lane & 3;      // 0..3
    const int wm   = wid & 1;       // 2 warps along M
    const int wn   = wid >> 1;      // 4 warps along N
    const int m0 = blockIdx.y * 128;
    const int n0 = blockIdx.x * 128;

    const uint32_t sbase = smem_u32(dsm);

    // load slots: per operand 512 (row,unit) slots; 2 per thread
    int rowi[2], uni[2];
    #pragma unroll
    for (int i = 0; i < 2; i++) {
        int lin = tid + 256 * i;
        rowi[i] = lin >> 2;
        uni[i]  = lin & 3;
    }

    auto load_chunk = [&](int c) {
        uint32_t sb = sbase + (uint32_t)(c % 3) * STG_BYTES;
        int kof = c * 32;
        #pragma unroll
        for (int i = 0; i < 2; i++) {
            int r = rowi[i], u = uni[i];
            uint32_t so = (uint32_t)(r * 80 + u * 16);
            size_t ga = (size_t)(m0 + r) * 1024 + kof + u * 8;
            size_t gb = (size_t)(n0 + r) * 1024 + kof + u * 8;
            cp_async16(sb + so,                 Ahi + ga);
            cp_async16(sb + OP_BYTES + so,      Alo + ga);
            cp_async16(sb + 2 * OP_BYTES + so,  Bhi + gb);
            cp_async16(sb + 3 * OP_BYTES + so,  Blo + gb);
        }
        CP_COMMIT();
    };

    load_chunk(0); load_chunk(1); load_chunk(2);

    float acc[4][4][4];
    #pragma unroll
    for (int mt = 0; mt < 4; mt++)
        #pragma unroll
        for (int nt = 0; nt < 4; nt++)
            #pragma unroll
            for (int r = 0; r < 4; r++) acc[mt][nt][r] = 0.f;

    #pragma unroll 1
    for (int c = 0; c < 32; c++) {
        if (c < 30)      cp_wait<2>();
        else if (c == 30) cp_wait<1>();
        else              cp_wait<0>();
        __syncthreads();

        uint32_t sb = sbase + (uint32_t)(c % 3) * STG_BYTES;
        #pragma unroll
        for (int kh = 0; kh < 2; kh++) {
            const uint32_t kb = kh * 32 + tig * 4;   // byte offset within row
            uint32_t ah[4][4], al[4][4], bh[4][2], bl[4][2];
            #pragma unroll
            for (int mt = 0; mt < 4; mt++) {
                uint32_t r0 = sb + (uint32_t)((wm * 64 + mt * 16 + g) * 80) + kb;
                uint32_t r1 = r0 + 8 * 80;
                ah[mt][0] = lds32(r0);      ah[mt][1] = lds32(r1);
                ah[mt][2] = lds32(r0 + 16); ah[mt][3] = lds32(r1 + 16);
                al[mt][0] = lds32(r0 + OP_BYTES);      al[mt][1] = lds32(r1 + OP_BYTES);
                al[mt][2] = lds32(r0 + OP_BYTES + 16); al[mt][3] = lds32(r1 + OP_BYTES + 16);
            }
            #pragma unroll
            for (int nt = 0; nt < 4; nt++) {
                uint32_t rb = sb + 2 * OP_BYTES + (uint32_t)((wn * 32 + nt * 8 + g) * 80) + kb;
                bh[nt][0] = lds32(rb);      bh[nt][1] = lds32(rb + 16);
                bl[nt][0] = lds32(rb + OP_BYTES);
                bl[nt][1] = lds32(rb + OP_BYTES + 16);
            }
            #pragma unroll
            for (int mt = 0; mt < 4; mt++)
                #pragma unroll
                for (int nt = 0; nt < 4; nt++) {
                    mma16816(acc[mt][nt], ah[mt], bh[nt]);
                    mma16816(acc[mt][nt], ah[mt], bl[nt]);
                    mma16816(acc[mt][nt], al[mt], bh[nt]);
                }
        }
        __syncthreads();
        if (c < 29) load_chunk(c + 3);
    }

    // epilogue: c0=(g,tig*2) c1=(g,tig*2+1) c2=(g+8,tig*2) c3=(g+8,tig*2+1)
    #pragma unroll
    for (int mt = 0; mt < 4; mt++) {
        int row = m0 + wm * 64 + mt * 16 + g;
        #pragma unroll
        for (int nt = 0; nt < 4; nt++) {
            int col = n0 + wn * 32 + nt * 8 + tig * 2;
            float b0 = bias[col], b1 = bias[col + 1];
            float2 w0 = make_float2(acc[mt][nt][0] + b0, acc[mt][nt][1] + b1);
            float2 w1 = make_float2(acc[mt][nt][2] + b0, acc[mt][nt][3] + b1);
            *(float2*)&C[(size_t)row * N + col]       = w0;
            *(float2*)&C[(size_t)(row + 8) * N + col] = w1;
        }
    }
}

// ======================= blocked ring attention (unchanged, passing) ======
__global__ void __launch_bounds__(256)
attn_kernel(const float* __restrict__ qkv, float* __restrict__ att)
{
    extern __shared__ float sm[];
    float* Qs = sm;                   // [64 d][68] transposed, pre-scaled
    float* Ks = Qs + 64 * 68;         // [64 k][65]
    float* Vs = Ks + 64 * 65;         // [64 k][68]
    float* Ps = Vs + 64 * 68;         // [64 q][68]

    const int tid    = threadIdx.x;
    const int lane16 = tid & 15;
    const int g16    = tid >> 4;
    const int q0     = g16 * 4;

    const int cta = blockIdx.x;
    const int qt  = cta & 7;
    const int blk = (cta >> 3) & 15;
    const int h   = (cta >> 7) & 15;
    const int b   = cta >> 11;

    const size_t rowbase = (size_t)b * 8192;
    const int s0   = blk * 512 + qt * 64;
    const int colQ = h * 64;
    const int colK = 1024 + h * 64;
    const int colV = 2048 + h * 64;

    {
        const float scale = 0.125f;
        #pragma unroll
        for (int it = 0; it < 4; it++) {
            int r  = g16 + 16 * it;
            int d4 = lane16 * 4;
            float4 v = *(const float4*)&qkv[(rowbase + s0 + r) * 3072 + colQ + d4];
            Qs[(d4 + 0) * 68 + r] = v.x * scale;
            Qs[(d4 + 1) * 68 + r] = v.y * scale;
            Qs[(d4 + 2) * 68 + r] = v.z * scale;
            Qs[(d4 + 3) * 68 + r] = v.w * scale;
        }
    }

    float4 kreg[4], vreg[4];
    auto load_chunk = [&](int c) {
        int pass = c >> 3;
        int kb   = pass ? ((blk + 1) & 15) : blk;
        int srow = kb * 512 + (c & 7) * 64;
        #pragma unroll
        for (int it = 0; it < 4; it++) {
            int r  = g16 + 16 * it;
            int d4 = lane16 * 4;
            size_t base = (rowbase + srow + r) * 3072;
            kreg[it] = *(const float4*)&qkv[base + colK + d4];
            vreg[it] = *(const float4*)&qkv[base + colV + d4];
        }
    };
    load_chunk(0);

    float m[4], l[4], ofin[4][4];
    ull oacc[4][2];
    #pragma unroll
    for (int i = 0; i < 4; i++) {
        m[i] = -1e30f; l[i] = 0.f;
        oacc[i][0] = oacc[i][1] = pk2(0.f, 0.f);
        #pragma unroll
        for (int j = 0; j < 4; j++) ofin[i][j] = 0.f;
    }

    for (int c = 0; c < 16; c++) {
        __syncthreads();
        #pragma unroll
        for (int it = 0; it < 4; it++) {
            int r  = g16 + 16 * it;
            int d4 = lane16 * 4;
            Ks[r * 65 + d4 + 0] = kreg[it].x;
            Ks[r * 65 + d4 + 1] = kreg[it].y;
            Ks[r * 65 + d4 + 2] = kreg[it].z;
            Ks[r * 65 + d4 + 3] = kreg[it].w;
            *(float4*)&Vs[r * 68 + d4] = vreg[it];
        }
        if (c < 15) load_chunk(c + 1);
        __syncthreads();

        ull sacc[4][2];
        #pragma unroll
        for (int i = 0; i < 4; i++) { sacc[i][0] = sacc[i][1] = pk2(0.f, 0.f); }
        #pragma unroll 16
        for (int d = 0; d < 64; d++) {
            float4 qv = *(const float4*)&Qs[d * 68 + q0];
            float k0v = Ks[(lane16     ) * 65 + d];
            float k1v = Ks[(lane16 + 16) * 65 + d];
            float k2v = Ks[(lane16 + 32) * 65 + d];
            float k3v = Ks[(lane16 + 48) * 65 + d];
            ull kp01 = pk2(k0v, k1v), kp23 = pk2(k2v, k3v);
            ull q0p = pk2(qv.x, qv.x), q1p = pk2(qv.y, qv.y);
            ull q2p = pk2(qv.z, qv.z), q3p = pk2(qv.w, qv.w);
            ffma2(sacc[0][0], q0p, kp01); ffma2(sacc[0][1], q0p, kp23);
            ffma2(sacc[1][0], q1p, kp01); ffma2(sacc[1][1], q1p, kp23);
            ffma2(sacc[2][0], q2p, kp01); ffma2(sacc[2][1], q2p, kp23);
            ffma2(sacc[3][0], q3p, kp01); ffma2(sacc[3][1], q3p, kp23);
        }

        #pragma unroll
        for (int i = 0; i < 4; i++) {
            float sv0, sv1, sv2, sv3;
            upk2(sacc[i][0], sv0, sv1);
            upk2(sacc[i][1], sv2, sv3);
            float cm = fmaxf(fmaxf(sv0, sv1), fmaxf(sv2, sv3));
            #pragma unroll
            for (int w = 8; w >= 1; w >>= 1)
                cm = fmaxf(cm, __shfl_xor_sync(0xffffffffu, cm, w));
            float mn    = fmaxf(m[i], cm);
            float alpha = __expf(m[i] - mn);
            float p0 = __expf(sv0 - mn), p1 = __expf(sv1 - mn);
            float p2 = __expf(sv2 - mn), p3 = __expf(sv3 - mn);
            float rs = p0 + p1 + p2 + p3;
            #pragma unroll
            for (int w = 8; w >= 1; w >>= 1)
                rs += __shfl_xor_sync(0xffffffffu, rs, w);
            l[i] = l[i] * alpha + rs;
            m[i] = mn;
            ull am = pk2(alpha, alpha);
            oacc[i][0] = fmul2(oacc[i][0], am);
            oacc[i][1] = fmul2(oacc[i][1], am);
            Ps[(q0 + i) * 68 + lane16     ] = p0;
            Ps[(q0 + i) * 68 + lane16 + 16] = p1;
            Ps[(q0 + i) * 68 + lane16 + 32] = p2;
            Ps[(q0 + i) * 68 + lane16 + 48] = p3;
        }
        __syncthreads();

        {
            const int d0 = lane16 * 4;
            #pragma unroll 16
            for (int k = 0; k < 64; k++) {
                float4 vv = *(const float4*)&Vs[k * 68 + d0];
                ull vp0 = pk2(vv.x, vv.y), vp1 = pk2(vv.z, vv.w);
                #pragma unroll
                for (int i = 0; i < 4; i++) {
                    float pv = Ps[(q0 + i) * 68 + k];
                    ull pp = pk2(pv, pv);
                    ffma2(oacc[i][0], pp, vp0);
                    ffma2(oacc[i][1], pp, vp1);
                }
            }
        }

        if ((c & 7) == 7) {
            #pragma unroll
            for (int i = 0; i < 4; i++) {
                float inv = 1.0f / l[i];
                float o0, o1, o2, o3;
                upk2(oacc[i][0], o0, o1);
                upk2(oacc[i][1], o2, o3);
                ofin[i][0] += o0 * inv; ofin[i][1] += o1 * inv;
                ofin[i][2] += o2 * inv; ofin[i][3] += o3 * inv;
                m[i] = -1e30f; l[i] = 0.f;
                oacc[i][0] = oacc[i][1] = pk2(0.f, 0.f);
            }
        }
    }

    {
        const int d0 = lane16 * 4;
        #pragma unroll
        for (int i = 0; i < 4; i++) {
            float4 w = make_float4(ofin[i][0], ofin[i][1], ofin[i][2], ofin[i][3]);
            *(float4*)&att[(rowbase + s0 + q0 + i) * 1024 + h * 64 + d0] = w;
        }
    }
}

// ============================ launcher ===================================
extern "C" void kernel_launch(void* const* d_in, const int* in_sizes, int n_in,
                              void* d_out, int out_size)
{
    const float* x    = (const float*)d_in[0];
    const float* Wqkv = (const float*)d_in[1];
    const float* bqkv = (const float*)d_in[2];
    const float* Wout = (const float*)d_in[3];
    const float* bout = (const float*)d_in[4];
    float* out = (float*)d_out;

    float* qkv; cudaGetSymbolAddress((void**)&qkv, g_qkv);
    float* att; cudaGetSymbolAddress((void**)&att, g_att);
    __nv_bfloat16 *xhi, *xlo, *whi, *wlo, *ahi, *alo, *ohi, *olo;
    cudaGetSymbolAddress((void**)&xhi, g_xhi);  cudaGetSymbolAddress((void**)&xlo, g_xlo);
    cudaGetSymbolAddress((void**)&whi, g_whi);  cudaGetSymbolAddress((void**)&wlo, g_wlo);
    cudaGetSymbolAddress((void**)&ahi, g_ahi);  cudaGetSymbolAddress((void**)&alo, g_alo);
    cudaGetSymbolAddress((void**)&ohi, g_ohi);  cudaGetSymbolAddress((void**)&olo, g_olo);

    const int gemm_smem = 3 * 40960;            // 122880 B
    cudaFuncSetAttribute(gemm_hmma_kernel, cudaFuncAttributeMaxDynamicSharedMemorySize,
                         gemm_smem);
    const int attn_smem = (64 * 68 + 64 * 65 + 64 * 68 + 64 * 68) * 4;  // 68864
    cudaFuncSetAttribute(attn_kernel, cudaFuncAttributeMaxDynamicSharedMemorySize,
                         attn_smem);

    // 0) operand conversion
    split_kernel<<<16384, 256>>>(x, xhi, xlo);
    transpose_split_kernel<<<dim3(3072 / 32, 1024 / 32), dim3(32, 8)>>>(
        Wqkv, whi, wlo, 1024, 3072);
    transpose_split_kernel<<<dim3(1024 / 32, 1024 / 32), dim3(32, 8)>>>(
        Wout, ohi, olo, 1024, 1024);

    // 1) qkv = x @ W_qkv + b_qkv   (HMMA bf16x3)
    gemm_hmma_kernel<<<dim3(3072 / 128, 16384 / 128), 256, gemm_smem>>>(
        xhi, xlo, whi, wlo, bqkv, qkv, 3072);

    // 2) blocked ring attention
    attn_kernel<<<4096, 256, attn_smem>>>(qkv, att);

    // 3) out = att @ W_out + b_out
    split_kernel<<<16384, 256>>>(att, ahi, alo);
    gemm_hmma_kernel<<<dim3(1024 / 128, 16384 / 128), 256, gemm_smem>>>(
        ahi, alo, ohi, olo, bout, out, 1024);
}

// round 5
// speedup vs baseline: 1.7790x; 1.3241x over previous
#include <cuda_runtime.h>
#include <cuda_bf16.h>
#include <cstdint>

typedef unsigned long long ull;

// ===================== PTX helpers (baseline, compute_103-safe) ==========
__device__ __forceinline__ uint32_t smem_u32(const void* p) {
    uint32_t a;
    asm("{ .reg .u64 t; cvta.to.shared.u64 t, %1; cvt.u32.u64 %0, t; }"
        : "=r"(a) : "l"(p));
    return a;
}
__device__ __forceinline__ void cp_async16(uint32_t dst, const void* src) {
    asm volatile("cp.async.cg.shared.global [%0], [%1], 16;" :: "r"(dst), "l"(src));
}
#define CP_COMMIT() asm volatile("cp.async.commit_group;" ::: "memory")
template <int N>
__device__ __forceinline__ void cp_wait() {
    asm volatile("cp.async.wait_group %0;" :: "n"(N) : "memory");
}
__device__ __forceinline__ uint32_t lds32(uint32_t a) {
    uint32_t v;
    asm volatile("ld.shared.b32 %0, [%1];" : "=r"(v) : "r"(a));
    return v;
}
// mma.sync m16n8k16 row.col bf16 -> f32
__device__ __forceinline__ void mma16816(float* d, const uint32_t* a, const uint32_t* b) {
    asm volatile(
        "mma.sync.aligned.m16n8k16.row.col.f32.bf16.bf16.f32 "
        "{%0,%1,%2,%3}, {%4,%5,%6,%7}, {%8,%9}, {%0,%1,%2,%3};"
        : "+f"(d[0]), "+f"(d[1]), "+f"(d[2]), "+f"(d[3])
        : "r"(a[0]), "r"(a[1]), "r"(a[2]), "r"(a[3]), "r"(b[0]), "r"(b[1]));
}
__device__ __forceinline__ float ex2f(float x) {
    float y; asm("ex2.approx.f32 %0, %1;" : "=f"(y) : "f"(x)); return y;
}
// pack two f32 -> bf16x2 (lo = second operand per PTX cvt semantics)
__device__ __forceinline__ uint32_t cvt_bf16x2(float hi, float lo) {
    uint32_t r;
    asm("cvt.rn.bf16x2.f32 %0, %1, %2;" : "=r"(r) : "f"(hi), "f"(lo));
    return r;
}

// ---------------- scratch (allocation-free rule: device globals) --------
__device__ float g_qkv[(size_t)16384 * 3072];          // 192 MB
__device__ float g_att[(size_t)16384 * 1024];          //  64 MB
__device__ __nv_bfloat16 g_xhi[(size_t)16384 * 1024];
__device__ __nv_bfloat16 g_xlo[(size_t)16384 * 1024];
__device__ __nv_bfloat16 g_whi[(size_t)3072 * 1024];   // W_qkv^T split
__device__ __nv_bfloat16 g_wlo[(size_t)3072 * 1024];
__device__ __nv_bfloat16 g_ahi[(size_t)16384 * 1024];
__device__ __nv_bfloat16 g_alo[(size_t)16384 * 1024];
__device__ __nv_bfloat16 g_ohi[(size_t)1024 * 1024];   // W_out^T split
__device__ __nv_bfloat16 g_olo[(size_t)1024 * 1024];
// attention operands (prep-kernel outputs)
__device__ __nv_bfloat16 g_qhi[(size_t)16384 * 1024];  // scaled by 0.125*log2e
__device__ __nv_bfloat16 g_qlo[(size_t)16384 * 1024];
__device__ __nv_bfloat16 g_khi[(size_t)16384 * 1024];
__device__ __nv_bfloat16 g_klo[(size_t)16384 * 1024];
__device__ __nv_bfloat16 g_vthi[(size_t)2 * 16 * 64 * 8192];  // [b][h][d][s]
__device__ __nv_bfloat16 g_vtlo[(size_t)2 * 16 * 64 * 8192];

// ===================== conversion kernels =====================
__global__ void __launch_bounds__(256)
split_kernel(const float* __restrict__ src, __nv_bfloat16* __restrict__ hi,
             __nv_bfloat16* __restrict__ lo)
{
    size_t i = ((size_t)blockIdx.x * 256 + threadIdx.x) * 4;
    float4 v = *(const float4*)(src + i);
    __nv_bfloat162* hp = (__nv_bfloat162*)(hi + i);
    __nv_bfloat162* lp = (__nv_bfloat162*)(lo + i);
    __nv_bfloat16 h0 = __float2bfloat16(v.x), h1 = __float2bfloat16(v.y);
    __nv_bfloat16 h2 = __float2bfloat16(v.z), h3 = __float2bfloat16(v.w);
    hp[0] = __nv_bfloat162(h0, h1);
    hp[1] = __nv_bfloat162(h2, h3);
    lp[0] = __nv_bfloat162(__float2bfloat16(v.x - __bfloat162float(h0)),
                           __float2bfloat16(v.y - __bfloat162float(h1)));
    lp[1] = __nv_bfloat162(__float2bfloat16(v.z - __bfloat162float(h2)),
                           __float2bfloat16(v.w - __bfloat162float(h3)));
}

// W [K,N] fp32 -> W^T [N,K] bf16 hi/lo
__global__ void __launch_bounds__(256)
transpose_split_kernel(const float* __restrict__ W, __nv_bfloat16* __restrict__ hiT,
                       __nv_bfloat16* __restrict__ loT, int K, int N)
{
    __shared__ float t[32][33];
    int n0 = blockIdx.x * 32, k0 = blockIdx.y * 32;
    int tx = threadIdx.x, ty = threadIdx.y;
    #pragma unroll
    for (int i = 0; i < 4; i++)
        t[ty + 8 * i][tx] = W[(size_t)(k0 + ty + 8 * i) * N + n0 + tx];
    __syncthreads();
    #pragma unroll
    for (int i = 0; i < 4; i++) {
        float v = t[tx][ty + 8 * i];
        __nv_bfloat16 h = __float2bfloat16(v);
        size_t o = (size_t)(n0 + ty + 8 * i) * K + k0 + tx;
        hiT[o] = h;
        loT[o] = __float2bfloat16(v - __bfloat162float(h));
    }
}

// q/k columns of qkv -> split bf16; q additionally scaled by 0.125*log2(e)
__global__ void __launch_bounds__(256)
qk_split_kernel(const float* __restrict__ qkv,
                __nv_bfloat16* __restrict__ qhi, __nv_bfloat16* __restrict__ qlo,
                __nv_bfloat16* __restrict__ khi, __nv_bfloat16* __restrict__ klo)
{
    size_t gid = (size_t)blockIdx.x * 256 + threadIdx.x;
    size_t row = gid >> 9;                 // 512 float4 per 2048-col region
    int c4 = (int)(gid & 511) * 4;
    float4 v = *(const float4*)&qkv[row * 3072 + c4];
    __nv_bfloat16 *hi, *lo;
    size_t o;
    if (c4 < 1024) {
        const float sc = 0.18033688011112042f;  // (1/8)*log2(e)
        v.x *= sc; v.y *= sc; v.z *= sc; v.w *= sc;
        o = row * 1024 + c4; hi = qhi; lo = qlo;
    } else {
        o = row * 1024 + c4 - 1024; hi = khi; lo = klo;
    }
    __nv_bfloat16 h0 = __float2bfloat16(v.x), h1 = __float2bfloat16(v.y);
    __nv_bfloat16 h2 = __float2bfloat16(v.z), h3 = __float2bfloat16(v.w);
    *(__nv_bfloat162*)&hi[o]     = __nv_bfloat162(h0, h1);
    *(__nv_bfloat162*)&hi[o + 2] = __nv_bfloat162(h2, h3);
    *(__nv_bfloat162*)&lo[o]     = __nv_bfloat162(__float2bfloat16(v.x - __bfloat162float(h0)),
                                                  __float2bfloat16(v.y - __bfloat162float(h1)));
    *(__nv_bfloat162*)&lo[o + 2] = __nv_bfloat162(__float2bfloat16(v.z - __bfloat162float(h2)),
                                                  __float2bfloat16(v.w - __bfloat162float(h3)));
}

// v columns of qkv -> per-head transpose [b][h][d][s], split bf16
__global__ void __launch_bounds__(256)
v_transpose_split_kernel(const float* __restrict__ qkv,
                         __nv_bfloat16* __restrict__ vthi,
                         __nv_bfloat16* __restrict__ vtlo)
{
    __shared__ float tbuf[32][33];
    int bh = blockIdx.z;
    int b = bh >> 4, h = bh & 15;
    int s0 = blockIdx.x * 32, d0 = blockIdx.y * 32;
    int tx = threadIdx.x, ty = threadIdx.y;   // 32 x 8
    #pragma unroll
    for (int i = 0; i < 4; i++)
        tbuf[ty + 8 * i][tx] =
            qkv[((size_t)b * 8192 + s0 + ty + 8 * i) * 3072 + 2048 + h * 64 + d0 + tx];
    __syncthreads();
    #pragma unroll
    for (int i = 0; i < 4; i++) {
        float v = tbuf[tx][ty + 8 * i];       // s = s0+tx, d = d0+ty+8i
        size_t o = ((size_t)bh * 64 + d0 + ty + 8 * i) * 8192 + s0 + tx;
        __nv_bfloat16 hv = __float2bfloat16(v);
        vthi[o] = hv;
        vtlo[o] = __float2bfloat16(v - __bfloat162float(hv));
    }
}

// ===================== HMMA bf16x3 GEMM (4-stage pipeline) =====================
#define OP_BYTES   10240u
#define STG_BYTES  40960u

__global__ void __launch_bounds__(256)
gemm_hmma_kernel(const __nv_bfloat16* __restrict__ Ahi, const __nv_bfloat16* __restrict__ Alo,
                 const __nv_bfloat16* __restrict__ Bhi, const __nv_bfloat16* __restrict__ Blo,
                 const float* __restrict__ bias, float* __restrict__ C, int N)
{
    extern __shared__ __align__(16) char dsm[];
    const int tid  = threadIdx.x;
    const int wid  = tid >> 5;
    const int lane = tid & 31;
    const int g    = lane >> 2;
    const int tig  = lane & 3;
    const int wm   = wid & 1;
    const int wn   = wid >> 1;
    const int m0 = blockIdx.y * 128;
    const int n0 = blockIdx.x * 128;

    const uint32_t sbase = smem_u32(dsm);

    int rowi[2], uni[2];
    #pragma unroll
    for (int i = 0; i < 2; i++) {
        int lin = tid + 256 * i;
        rowi[i] = lin >> 2;
        uni[i]  = lin & 3;
    }

    auto load_chunk = [&](int c) {
        uint32_t sb = sbase + (uint32_t)(c & 3) * STG_BYTES;
        int kof = c * 32;
        #pragma unroll
        for (int i = 0; i < 2; i++) {
            int r = rowi[i], u = uni[i];
            uint32_t so = (uint32_t)(r * 80 + u * 16);
            size_t ga = (size_t)(m0 + r) * 1024 + kof + u * 8;
            size_t gb = (size_t)(n0 + r) * 1024 + kof + u * 8;
            cp_async16(sb + so,                 Ahi + ga);
            cp_async16(sb + OP_BYTES + so,      Alo + ga);
            cp_async16(sb + 2 * OP_BYTES + so,  Bhi + gb);
            cp_async16(sb + 3 * OP_BYTES + so,  Blo + gb);
        }
        CP_COMMIT();
    };

    load_chunk(0); load_chunk(1); load_chunk(2);

    float acc[4][4][4];
    #pragma unroll
    for (int mt = 0; mt < 4; mt++)
        #pragma unroll
        for (int nt = 0; nt < 4; nt++)
            #pragma unroll
            for (int r = 0; r < 4; r++) acc[mt][nt][r] = 0.f;

    #pragma unroll 1
    for (int c = 0; c < 32; c++) {
        if (c < 30)       cp_wait<2>();
        else if (c == 30) cp_wait<1>();
        else              cp_wait<0>();
        __syncthreads();
        if (c < 29) load_chunk(c + 3);   // loads overlap the MMAs below

        uint32_t sb = sbase + (uint32_t)(c & 3) * STG_BYTES;
        #pragma unroll
        for (int kh = 0; kh < 2; kh++) {
            const uint32_t kb = kh * 32 + tig * 4;
            uint32_t ah[4][4], al[4][4], bh[4][2], bl[4][2];
            #pragma unroll
            for (int mt = 0; mt < 4; mt++) {
                uint32_t r0 = sb + (uint32_t)((wm * 64 + mt * 16 + g) * 80) + kb;
                uint32_t r1 = r0 + 8 * 80;
                ah[mt][0] = lds32(r0);      ah[mt][1] = lds32(r1);
                ah[mt][2] = lds32(r0 + 16); ah[mt][3] = lds32(r1 + 16);
                al[mt][0] = lds32(r0 + OP_BYTES);      al[mt][1] = lds32(r1 + OP_BYTES);
                al[mt][2] = lds32(r0 + OP_BYTES + 16); al[mt][3] = lds32(r1 + OP_BYTES + 16);
            }
            #pragma unroll
            for (int nt = 0; nt < 4; nt++) {
                uint32_t rb = sb + 2 * OP_BYTES + (uint32_t)((wn * 32 + nt * 8 + g) * 80) + kb;
                bh[nt][0] = lds32(rb);      bh[nt][1] = lds32(rb + 16);
                bl[nt][0] = lds32(rb + OP_BYTES);
                bl[nt][1] = lds32(rb + OP_BYTES + 16);
            }
            // combo-major: 16 independent accumulators between reuses
            #pragma unroll
            for (int mt = 0; mt < 4; mt++)
                #pragma unroll
                for (int nt = 0; nt < 4; nt++) mma16816(acc[mt][nt], ah[mt], bh[nt]);
            #pragma unroll
            for (int mt = 0; mt < 4; mt++)
                #pragma unroll
                for (int nt = 0; nt < 4; nt++) mma16816(acc[mt][nt], ah[mt], bl[nt]);
            #pragma unroll
            for (int mt = 0; mt < 4; mt++)
                #pragma unroll
                for (int nt = 0; nt < 4; nt++) mma16816(acc[mt][nt], al[mt], bh[nt]);
        }
        __syncthreads();
    }

    #pragma unroll
    for (int mt = 0; mt < 4; mt++) {
        int row = m0 + wm * 64 + mt * 16 + g;
        #pragma unroll
        for (int nt = 0; nt < 4; nt++) {
            int col = n0 + wn * 32 + nt * 8 + tig * 2;
            float b0 = bias[col], b1 = bias[col + 1];
            float2 w0 = make_float2(acc[mt][nt][0] + b0, acc[mt][nt][1] + b1);
            float2 w1 = make_float2(acc[mt][nt][2] + b0, acc[mt][nt][3] + b1);
            *(float2*)&C[(size_t)row * N + col]       = w0;
            *(float2*)&C[(size_t)(row + 8) * N + col] = w1;
        }
    }
}

// ===================== HMMA blocked ring attention =====================
// grid 4096 = (qt:8, blk:16, h:16, b:2); 128 threads (4 warps x 16 q-rows).
// Q/K bf16 hi/lo (Q pre-scaled into exp2 domain); V^T bf16 hi/lo.
// Two flash passes (local block, next block), outputs summed.
__global__ void __launch_bounds__(128)
attn_hmma_kernel(const __nv_bfloat16* __restrict__ Qhi_g, const __nv_bfloat16* __restrict__ Qlo_g,
                 const __nv_bfloat16* __restrict__ Khi_g, const __nv_bfloat16* __restrict__ Klo_g,
                 const __nv_bfloat16* __restrict__ Vthi_g, const __nv_bfloat16* __restrict__ Vtlo_g,
                 float* __restrict__ att)
{
    extern __shared__ __align__(16) char dsm[];
    const int tid  = threadIdx.x;
    const int w    = tid >> 5;
    const int lane = tid & 31;
    const int g    = lane >> 2;
    const int t    = lane & 3;

    const int cta = blockIdx.x;
    const int qt  = cta & 7;
    const int blk = (cta >> 3) & 15;
    const int h   = (cta >> 7) & 15;
    const int b   = cta >> 11;
    const size_t rowbase = (size_t)b * 8192;
    const int s0 = blk * 512 + qt * 64;
    const int bh = b * 16 + h;

    // smem: rows of 64 bf16 padded to 72 (144 B); tiles of 64 rows = 9216 B
    const uint32_t sQ = smem_u32(dsm);       // Qhi, Qlo(+9216)
    const uint32_t sK = sQ + 18432;          // 2 stages x (Khi,Klo) = 18432 each
    const uint32_t sV = sQ + 55296;          // 2 stages x (Vthi,Vtlo)

    const int lr = tid >> 1;                 // 0..63
    const int lh = tid & 1;

    // ---- Q load (grouped with chunk 0) ----
    {
        const __nv_bfloat16* qh = Qhi_g + (rowbase + s0 + lr) * 1024 + h * 64 + lh * 32;
        const __nv_bfloat16* ql = Qlo_g + (rowbase + s0 + lr) * 1024 + h * 64 + lh * 32;
        uint32_t d = sQ + lr * 144 + lh * 64;
        #pragma unroll
        for (int j = 0; j < 4; j++) {
            cp_async16(d + j * 16,        qh + j * 8);
            cp_async16(d + 9216 + j * 16, ql + j * 8);
        }
    }
    auto load_kv = [&](int c) {
        int stage = c & 1;
        int kb2   = (c >= 8) ? ((blk + 1) & 15) : blk;
        int sk    = kb2 * 512 + (c & 7) * 64;
        const __nv_bfloat16* kh = Khi_g + (rowbase + sk + lr) * 1024 + h * 64 + lh * 32;
        const __nv_bfloat16* kl = Klo_g + (rowbase + sk + lr) * 1024 + h * 64 + lh * 32;
        uint32_t kd = sK + stage * 18432 + lr * 144 + lh * 64;
        #pragma unroll
        for (int j = 0; j < 4; j++) {
            cp_async16(kd + j * 16,        kh + j * 8);
            cp_async16(kd + 9216 + j * 16, kl + j * 8);
        }
        const __nv_bfloat16* vh = Vthi_g + ((size_t)bh * 64 + lr) * 8192 + sk + lh * 32;
        const __nv_bfloat16* vl = Vtlo_g + ((size_t)bh * 64 + lr) * 8192 + sk + lh * 32;
        uint32_t vd = sV + stage * 18432 + lr * 144 + lh * 64;
        #pragma unroll
        for (int j = 0; j < 4; j++) {
            cp_async16(vd + j * 16,        vh + j * 8);
            cp_async16(vd + 9216 + j * 16, vl + j * 8);
        }
        CP_COMMIT();
    };
    load_kv(0);
    load_kv(1);

    float m0 = -1e30f, m1 = -1e30f, l0 = 0.f, l1 = 0.f;
    float oacc[8][4], ofin[8][4];
    #pragma unroll
    for (int nt = 0; nt < 8; nt++)
        #pragma unroll
        for (int j = 0; j < 4; j++) { oacc[nt][j] = 0.f; ofin[nt][j] = 0.f; }

    #pragma unroll 1
    for (int c = 0; c < 16; c++) {
        cp_wait<1>();
        __syncthreads();
        const uint32_t kb = sK + (c & 1) * 18432;
        const uint32_t vb = sV + (c & 1) * 18432;

        // ---- S = Q K^T (m16 x n64, k=64, bf16x3) ----
        float sacc[8][4];
        #pragma unroll
        for (int nt = 0; nt < 8; nt++)
            #pragma unroll
            for (int j = 0; j < 4; j++) sacc[nt][j] = 0.f;

        #pragma unroll
        for (int ks = 0; ks < 4; ks++) {
            uint32_t qa = sQ + (uint32_t)((w * 16 + g) * 144) + ks * 32 + t * 4;
            uint32_t ah[4], al[4];
            ah[0] = lds32(qa);        ah[1] = lds32(qa + 8 * 144);
            ah[2] = lds32(qa + 16);   ah[3] = lds32(qa + 8 * 144 + 16);
            al[0] = lds32(qa + 9216); al[1] = lds32(qa + 9216 + 8 * 144);
            al[2] = lds32(qa + 9216 + 16); al[3] = lds32(qa + 9216 + 8 * 144 + 16);
            uint32_t kf[8][2], klf[8][2];
            #pragma unroll
            for (int nt = 0; nt < 8; nt++) {
                uint32_t ka = kb + (uint32_t)((nt * 8 + g) * 144) + ks * 32 + t * 4;
                kf[nt][0]  = lds32(ka);        kf[nt][1]  = lds32(ka + 16);
                klf[nt][0] = lds32(ka + 9216); klf[nt][1] = lds32(ka + 9216 + 16);
            }
            #pragma unroll
            for (int nt = 0; nt < 8; nt++) mma16816(sacc[nt], ah, kf[nt]);
            #pragma unroll
            for (int nt = 0; nt < 8; nt++) mma16816(sacc[nt], ah, klf[nt]);
            #pragma unroll
            for (int nt = 0; nt < 8; nt++) mma16816(sacc[nt], al, kf[nt]);
        }

        // ---- online softmax in exp2 domain (rows r0 = g, r1 = g+8) ----
        float mx0 = -1e30f, mx1 = -1e30f;
        #pragma unroll
        for (int nt = 0; nt < 8; nt++) {
            mx0 = fmaxf(mx0, fmaxf(sacc[nt][0], sacc[nt][1]));
            mx1 = fmaxf(mx1, fmaxf(sacc[nt][2], sacc[nt][3]));
        }
        mx0 = fmaxf(mx0, __shfl_xor_sync(0xffffffffu, mx0, 1));
        mx0 = fmaxf(mx0, __shfl_xor_sync(0xffffffffu, mx0, 2));
        mx1 = fmaxf(mx1, __shfl_xor_sync(0xffffffffu, mx1, 1));
        mx1 = fmaxf(mx1, __shfl_xor_sync(0xffffffffu, mx1, 2));
        float mn0 = fmaxf(m0, mx0), mn1 = fmaxf(m1, mx1);
        float alpha0 = ex2f(m0 - mn0), alpha1 = ex2f(m1 - mn1);
        float rs0 = 0.f, rs1 = 0.f;
        #pragma unroll
        for (int nt = 0; nt < 8; nt++) {
            sacc[nt][0] = ex2f(sacc[nt][0] - mn0);
            sacc[nt][1] = ex2f(sacc[nt][1] - mn0);
            sacc[nt][2] = ex2f(sacc[nt][2] - mn1);
            sacc[nt][3] = ex2f(sacc[nt][3] - mn1);
            rs0 += sacc[nt][0] + sacc[nt][1];
            rs1 += sacc[nt][2] + sacc[nt][3];
        }
        rs0 += __shfl_xor_sync(0xffffffffu, rs0, 1);
        rs0 += __shfl_xor_sync(0xffffffffu, rs0, 2);
        rs1 += __shfl_xor_sync(0xffffffffu, rs1, 1);
        rs1 += __shfl_xor_sync(0xffffffffu, rs1, 2);
        l0 = l0 * alpha0 + rs0;
        l1 = l1 * alpha1 + rs1;
        m0 = mn0; m1 = mn1;
        #pragma unroll
        for (int nt = 0; nt < 8; nt++) {
            oacc[nt][0] *= alpha0; oacc[nt][1] *= alpha0;
            oacc[nt][2] *= alpha1; oacc[nt][3] *= alpha1;
        }

        // ---- O += P V (P hi/lo built in registers from sacc) ----
        #pragma unroll
        for (int ks = 0; ks < 4; ks++) {
            uint32_t ph[4], pl[4];
            #pragma unroll
            for (int half = 0; half < 2; half++) {
                const float* s2 = sacc[2 * ks + half];
                uint32_t h01 = cvt_bf16x2(s2[1], s2[0]);
                uint32_t h23 = cvt_bf16x2(s2[3], s2[2]);
                float f0 = __uint_as_float(h01 << 16);
                float f1 = __uint_as_float(h01 & 0xffff0000u);
                float f2 = __uint_as_float(h23 << 16);
                float f3 = __uint_as_float(h23 & 0xffff0000u);
                ph[2 * half]     = h01;   // a0/a2: row g
                ph[2 * half + 1] = h23;   // a1/a3: row g+8
                pl[2 * half]     = cvt_bf16x2(s2[1] - f1, s2[0] - f0);
                pl[2 * half + 1] = cvt_bf16x2(s2[3] - f3, s2[2] - f2);
            }
            // reorder to A-frag convention: {rowg k0, rowg+8 k0, rowg k8, rowg+8 k8}
            uint32_t pA[4] = { ph[0], ph[1], ph[2], ph[3] };
            uint32_t pL[4] = { pl[0], pl[1], pl[2], pl[3] };
            uint32_t vf[8][2], vlf[8][2];
            #pragma unroll
            for (int nt = 0; nt < 8; nt++) {
                uint32_t va = vb + (uint32_t)((nt * 8 + g) * 144) + ks * 32 + t * 4;
                vf[nt][0]  = lds32(va);        vf[nt][1]  = lds32(va + 16);
                vlf[nt][0] = lds32(va + 9216); vlf[nt][1] = lds32(va + 9216 + 16);
            }
            #pragma unroll
            for (int nt = 0; nt < 8; nt++) mma16816(oacc[nt], pA, vf[nt]);
            #pragma unroll
            for (int nt = 0; nt < 8; nt++) mma16816(oacc[nt], pA, vlf[nt]);
            #pragma unroll
            for (int nt = 0; nt < 8; nt++) mma16816(oacc[nt], pL, vf[nt]);
        }

        __syncthreads();
        if (c < 14) load_kv(c + 2);

        // ---- pass boundary: normalize + accumulate ----
        if ((c & 7) == 7) {
            float i0 = 1.0f / l0, i1 = 1.0f / l1;
            #pragma unroll
            for (int nt = 0; nt < 8; nt++) {
                ofin[nt][0] += oacc[nt][0] * i0;
                ofin[nt][1] += oacc[nt][1] * i0;
                ofin[nt][2] += oacc[nt][2] * i1;
                ofin[nt][3] += oacc[nt][3] * i1;
                oacc[nt][0] = oacc[nt][1] = oacc[nt][2] = oacc[nt][3] = 0.f;
            }
            m0 = m1 = -1e30f;
            l0 = l1 = 0.f;
        }
    }

    // ---- store O fp32 ----
    size_t r0 = rowbase + s0 + w * 16 + g;
    #pragma unroll
    for (int nt = 0; nt < 8; nt++) {
        int col = h * 64 + nt * 8 + t * 2;
        *(float2*)&att[r0 * 1024 + col]       = make_float2(ofin[nt][0], ofin[nt][1]);
        *(float2*)&att[(r0 + 8) * 1024 + col] = make_float2(ofin[nt][2], ofin[nt][3]);
    }
}

// ============================ launcher ===================================
extern "C" void kernel_launch(void* const* d_in, const int* in_sizes, int n_in,
                              void* d_out, int out_size)
{
    const float* x    = (const float*)d_in[0];
    const float* Wqkv = (const float*)d_in[1];
    const float* bqkv = (const float*)d_in[2];
    const float* Wout = (const float*)d_in[3];
    const float* bout = (const float*)d_in[4];
    float* out = (float*)d_out;

    float* qkv; cudaGetSymbolAddress((void**)&qkv, g_qkv);
    float* att; cudaGetSymbolAddress((void**)&att, g_att);
    __nv_bfloat16 *xhi, *xlo, *whi, *wlo, *ahi, *alo, *ohi, *olo;
    __nv_bfloat16 *qhi, *qlo, *khi, *klo, *vthi, *vtlo;
    cudaGetSymbolAddress((void**)&xhi, g_xhi);  cudaGetSymbolAddress((void**)&xlo, g_xlo);
    cudaGetSymbolAddress((void**)&whi, g_whi);  cudaGetSymbolAddress((void**)&wlo, g_wlo);
    cudaGetSymbolAddress((void**)&ahi, g_ahi);  cudaGetSymbolAddress((void**)&alo, g_alo);
    cudaGetSymbolAddress((void**)&ohi, g_ohi);  cudaGetSymbolAddress((void**)&olo, g_olo);
    cudaGetSymbolAddress((void**)&qhi, g_qhi);  cudaGetSymbolAddress((void**)&qlo, g_qlo);
    cudaGetSymbolAddress((void**)&khi, g_khi);  cudaGetSymbolAddress((void**)&klo, g_klo);
    cudaGetSymbolAddress((void**)&vthi, g_vthi); cudaGetSymbolAddress((void**)&vtlo, g_vtlo);

    const int gemm_smem = 4 * 40960;   // 163840 B
    cudaFuncSetAttribute(gemm_hmma_kernel, cudaFuncAttributeMaxDynamicSharedMemorySize,
                         gemm_smem);
    const int attn_smem = 92160;       // Q(hi/lo) + 2-stage K(hi/lo) + 2-stage Vt(hi/lo)
    cudaFuncSetAttribute(attn_hmma_kernel, cudaFuncAttributeMaxDynamicSharedMemorySize,
                         attn_smem);

    // 0) operand conversion for gemm1
    split_kernel<<<16384, 256>>>(x, xhi, xlo);
    transpose_split_kernel<<<dim3(3072 / 32, 1024 / 32), dim3(32, 8)>>>(
        Wqkv, whi, wlo, 1024, 3072);
    transpose_split_kernel<<<dim3(1024 / 32, 1024 / 32), dim3(32, 8)>>>(
        Wout, ohi, olo, 1024, 1024);

    // 1) qkv = x @ W_qkv + b_qkv   (HMMA bf16x3)
    gemm_hmma_kernel<<<dim3(3072 / 128, 16384 / 128), 256, gemm_smem>>>(
        xhi, xlo, whi, wlo, bqkv, qkv, 3072);

    // 2) attention operand prep
    qk_split_kernel<<<32768, 256>>>(qkv, qhi, qlo, khi, klo);
    v_transpose_split_kernel<<<dim3(256, 2, 32), dim3(32, 8)>>>(qkv, vthi, vtlo);

    // 3) blocked ring attention (HMMA)
    attn_hmma_kernel<<<4096, 128, attn_smem>>>(qhi, qlo, khi, klo, vthi, vtlo, att);

    // 4) out = att @ W_out + b_out
    split_kernel<<<16384, 256>>>(att, ahi, alo);
    gemm_hmma_kernel<<<dim3(1024 / 128, 16384 / 128), 256, gemm_smem>>>(
        ahi, alo, ohi, olo, bout, out, 1024);
}

// round 6
// speedup vs baseline: 2.1818x; 1.2264x over previous
#include <cuda_runtime.h>
#include <cuda_bf16.h>
#include <cstdint>

typedef unsigned long long ull;

// ===================== PTX helpers (baseline, compute_103-safe) ==========
__device__ __forceinline__ uint32_t smem_u32(const void* p) {
    uint32_t a;
    asm("{ .reg .u64 t; cvta.to.shared.u64 t, %1; cvt.u32.u64 %0, t; }"
        : "=r"(a) : "l"(p));
    return a;
}
__device__ __forceinline__ void cp_async16(uint32_t dst, const void* src) {
    asm volatile("cp.async.cg.shared.global [%0], [%1], 16;" :: "r"(dst), "l"(src));
}
#define CP_COMMIT() asm volatile("cp.async.commit_group;" ::: "memory")
template <int N>
__device__ __forceinline__ void cp_wait() {
    asm volatile("cp.async.wait_group %0;" :: "n"(N) : "memory");
}
__device__ __forceinline__ uint32_t lds32(uint32_t a) {
    uint32_t v;
    asm volatile("ld.shared.b32 %0, [%1];" : "=r"(v) : "r"(a));
    return v;
}
// mma.sync m16n8k16 row.col bf16 -> f32
__device__ __forceinline__ void mma16816(float* d, const uint32_t* a, const uint32_t* b) {
    asm volatile(
        "mma.sync.aligned.m16n8k16.row.col.f32.bf16.bf16.f32 "
        "{%0,%1,%2,%3}, {%4,%5,%6,%7}, {%8,%9}, {%0,%1,%2,%3};"
        : "+f"(d[0]), "+f"(d[1]), "+f"(d[2]), "+f"(d[3])
        : "r"(a[0]), "r"(a[1]), "r"(a[2]), "r"(a[3]), "r"(b[0]), "r"(b[1]));
}
__device__ __forceinline__ float ex2f(float x) {
    float y; asm("ex2.approx.f32 %0, %1;" : "=f"(y) : "f"(x)); return y;
}
// pack two f32 -> bf16x2 (second operand lands in the LOW half)
__device__ __forceinline__ uint32_t cvt_bf16x2(float hi, float lo) {
    uint32_t r;
    asm("cvt.rn.bf16x2.f32 %0, %1, %2;" : "=r"(r) : "f"(hi), "f"(lo));
    return r;
}
// split two fp32 into bf16x2 hi-word + bf16x2 residual-word
__device__ __forceinline__ void split2(float v0, float v1, uint32_t& hw, uint32_t& lw) {
    hw = cvt_bf16x2(v1, v0);
    float f0 = __uint_as_float(hw << 16);
    float f1 = __uint_as_float(hw & 0xffff0000u);
    lw = cvt_bf16x2(v1 - f1, v0 - f0);
}

// ---------------- scratch (allocation-free rule: device globals) --------
__device__ float g_qkv[(size_t)16384 * 3072];          // fp32 (v cols used)
__device__ __nv_bfloat16 g_xhi[(size_t)16384 * 1024];
__device__ __nv_bfloat16 g_xlo[(size_t)16384 * 1024];
__device__ __nv_bfloat16 g_whi[(size_t)3072 * 1024];   // W_qkv^T split
__device__ __nv_bfloat16 g_wlo[(size_t)3072 * 1024];
__device__ __nv_bfloat16 g_ahi[(size_t)16384 * 1024];  // attention out split
__device__ __nv_bfloat16 g_alo[(size_t)16384 * 1024];
__device__ __nv_bfloat16 g_ohi[(size_t)1024 * 1024];   // W_out^T split
__device__ __nv_bfloat16 g_olo[(size_t)1024 * 1024];
__device__ __nv_bfloat16 g_qhi[(size_t)16384 * 1024];  // scaled by 0.125*log2e
__device__ __nv_bfloat16 g_qlo[(size_t)16384 * 1024];
__device__ __nv_bfloat16 g_khi[(size_t)16384 * 1024];
__device__ __nv_bfloat16 g_klo[(size_t)16384 * 1024];
__device__ __nv_bfloat16 g_vthi[(size_t)2 * 16 * 64 * 8192];  // [b][h][d][s]
__device__ __nv_bfloat16 g_vtlo[(size_t)2 * 16 * 64 * 8192];

// ===================== conversion kernels =====================
__global__ void __launch_bounds__(256)
split_kernel(const float* __restrict__ src, __nv_bfloat16* __restrict__ hi,
             __nv_bfloat16* __restrict__ lo)
{
    size_t i = ((size_t)blockIdx.x * 256 + threadIdx.x) * 4;
    float4 v = *(const float4*)(src + i);
    uint32_t h0, l0w, h1, l1w;
    split2(v.x, v.y, h0, l0w);
    split2(v.z, v.w, h1, l1w);
    ((uint32_t*)(hi + i))[0] = h0; ((uint32_t*)(hi + i))[1] = h1;
    ((uint32_t*)(lo + i))[0] = l0w; ((uint32_t*)(lo + i))[1] = l1w;
}

// W [K,N] fp32 -> W^T [N,K] bf16 hi/lo
__global__ void __launch_bounds__(256)
transpose_split_kernel(const float* __restrict__ W, __nv_bfloat16* __restrict__ hiT,
                       __nv_bfloat16* __restrict__ loT, int K, int N)
{
    __shared__ float t[32][33];
    int n0 = blockIdx.x * 32, k0 = blockIdx.y * 32;
    int tx = threadIdx.x, ty = threadIdx.y;
    #pragma unroll
    for (int i = 0; i < 4; i++)
        t[ty + 8 * i][tx] = W[(size_t)(k0 + ty + 8 * i) * N + n0 + tx];
    __syncthreads();
    #pragma unroll
    for (int i = 0; i < 4; i++) {
        float v = t[tx][ty + 8 * i];
        __nv_bfloat16 h = __float2bfloat16(v);
        size_t o = (size_t)(n0 + ty + 8 * i) * K + k0 + tx;
        hiT[o] = h;
        loT[o] = __float2bfloat16(v - __bfloat162float(h));
    }
}

// v columns of qkv -> per-head transpose [b][h][d][s], split bf16
__global__ void __launch_bounds__(256)
v_transpose_split_kernel(const float* __restrict__ qkv,
                         __nv_bfloat16* __restrict__ vthi,
                         __nv_bfloat16* __restrict__ vtlo)
{
    __shared__ float tbuf[32][33];
    int bh = blockIdx.z;
    int b = bh >> 4, h = bh & 15;
    int s0 = blockIdx.x * 32, d0 = blockIdx.y * 32;
    int tx = threadIdx.x, ty = threadIdx.y;   // 32 x 8
    #pragma unroll
    for (int i = 0; i < 4; i++)
        tbuf[ty + 8 * i][tx] =
            qkv[((size_t)b * 8192 + s0 + ty + 8 * i) * 3072 + 2048 + h * 64 + d0 + tx];
    __syncthreads();
    #pragma unroll
    for (int i = 0; i < 4; i++) {
        float v = tbuf[tx][ty + 8 * i];       // s = s0+tx, d = d0+ty+8i
        size_t o = ((size_t)bh * 64 + d0 + ty + 8 * i) * 8192 + s0 + tx;
        __nv_bfloat16 hv = __float2bfloat16(v);
        vthi[o] = hv;
        vtlo[o] = __float2bfloat16(v - __bfloat162float(hv));
    }
}

// ===================== HMMA bf16x3 GEMM (2-stage, 2 CTA/SM) ================
#define OP_BYTES   10240u
#define STG_BYTES  40960u

__global__ void __launch_bounds__(256)
gemm_hmma_kernel(const __nv_bfloat16* __restrict__ Ahi, const __nv_bfloat16* __restrict__ Alo,
                 const __nv_bfloat16* __restrict__ Bhi, const __nv_bfloat16* __restrict__ Blo,
                 const float* __restrict__ bias, float* __restrict__ C, int N, int mode,
                 __nv_bfloat16* __restrict__ qhi, __nv_bfloat16* __restrict__ qlo,
                 __nv_bfloat16* __restrict__ khi, __nv_bfloat16* __restrict__ klo)
{
    extern __shared__ __align__(16) char dsm[];
    const int tid  = threadIdx.x;
    const int wid  = tid >> 5;
    const int lane = tid & 31;
    const int g    = lane >> 2;
    const int tig  = lane & 3;
    const int wm   = wid & 1;
    const int wn   = wid >> 1;
    const int m0 = blockIdx.y * 128;
    const int n0 = blockIdx.x * 128;

    const uint32_t sbase = smem_u32(dsm);

    int rowi[2], uni[2];
    #pragma unroll
    for (int i = 0; i < 2; i++) {
        int lin = tid + 256 * i;
        rowi[i] = lin >> 2;
        uni[i]  = lin & 3;
    }

    auto load_chunk = [&](int c) {
        uint32_t sb = sbase + (uint32_t)(c & 1) * STG_BYTES;
        int kof = c * 32;
        #pragma unroll
        for (int i = 0; i < 2; i++) {
            int r = rowi[i], u = uni[i];
            uint32_t so = (uint32_t)(r * 80 + u * 16);
            size_t ga = (size_t)(m0 + r) * 1024 + kof + u * 8;
            size_t gb = (size_t)(n0 + r) * 1024 + kof + u * 8;
            cp_async16(sb + so,                 Ahi + ga);
            cp_async16(sb + OP_BYTES + so,      Alo + ga);
            cp_async16(sb + 2 * OP_BYTES + so,  Bhi + gb);
            cp_async16(sb + 3 * OP_BYTES + so,  Blo + gb);
        }
        CP_COMMIT();
    };

    load_chunk(0); load_chunk(1);

    float acc[4][4][4];
    #pragma unroll
    for (int mt = 0; mt < 4; mt++)
        #pragma unroll
        for (int nt = 0; nt < 4; nt++)
            #pragma unroll
            for (int r = 0; r < 4; r++) acc[mt][nt][r] = 0.f;

    #pragma unroll 1
    for (int c = 0; c < 32; c++) {
        if (c < 31) cp_wait<1>();
        else        cp_wait<0>();
        __syncthreads();

        uint32_t sb = sbase + (uint32_t)(c & 1) * STG_BYTES;
        #pragma unroll
        for (int kh = 0; kh < 2; kh++) {
            const uint32_t kb = kh * 32 + tig * 4;
            uint32_t ah[4][4], al[4][4], bh[4][2], bl[4][2];
            #pragma unroll
            for (int mt = 0; mt < 4; mt++) {
                uint32_t r0 = sb + (uint32_t)((wm * 64 + mt * 16 + g) * 80) + kb;
                uint32_t r1 = r0 + 8 * 80;
                ah[mt][0] = lds32(r0);      ah[mt][1] = lds32(r1);
                ah[mt][2] = lds32(r0 + 16); ah[mt][3] = lds32(r1 + 16);
                al[mt][0] = lds32(r0 + OP_BYTES);      al[mt][1] = lds32(r1 + OP_BYTES);
                al[mt][2] = lds32(r0 + OP_BYTES + 16); al[mt][3] = lds32(r1 + OP_BYTES + 16);
            }
            #pragma unroll
            for (int nt = 0; nt < 4; nt++) {
                uint32_t rb = sb + 2 * OP_BYTES + (uint32_t)((wn * 32 + nt * 8 + g) * 80) + kb;
                bh[nt][0] = lds32(rb);      bh[nt][1] = lds32(rb + 16);
                bl[nt][0] = lds32(rb + OP_BYTES);
                bl[nt][1] = lds32(rb + OP_BYTES + 16);
            }
            #pragma unroll
            for (int mt = 0; mt < 4; mt++)
                #pragma unroll
                for (int nt = 0; nt < 4; nt++) mma16816(acc[mt][nt], ah[mt], bh[nt]);
            #pragma unroll
            for (int mt = 0; mt < 4; mt++)
                #pragma unroll
                for (int nt = 0; nt < 4; nt++) mma16816(acc[mt][nt], ah[mt], bl[nt]);
            #pragma unroll
            for (int mt = 0; mt < 4; mt++)
                #pragma unroll
                for (int nt = 0; nt < 4; nt++) mma16816(acc[mt][nt], al[mt], bh[nt]);
        }
        __syncthreads();
        if (c < 30) load_chunk(c + 2);
    }

    const float qsc = 0.18033688011112042f;   // (1/8)*log2(e)
    #pragma unroll
    for (int mt = 0; mt < 4; mt++) {
        int row = m0 + wm * 64 + mt * 16 + g;
        #pragma unroll
        for (int nt = 0; nt < 4; nt++) {
            int col = n0 + wn * 32 + nt * 8 + tig * 2;
            float b0 = bias[col], b1 = bias[col + 1];
            float v00 = acc[mt][nt][0] + b0, v01 = acc[mt][nt][1] + b1;
            float v10 = acc[mt][nt][2] + b0, v11 = acc[mt][nt][3] + b1;
            if (mode == 1 && col < 2048) {
                bool isq = col < 1024;
                float s = isq ? qsc : 1.f;
                __nv_bfloat16* hp = isq ? qhi : khi;
                __nv_bfloat16* lp = isq ? qlo : klo;
                int cc = col & 1023;
                uint32_t hw, lw;
                split2(v00 * s, v01 * s, hw, lw);
                *(uint32_t*)&hp[(size_t)row * 1024 + cc] = hw;
                *(uint32_t*)&lp[(size_t)row * 1024 + cc] = lw;
                split2(v10 * s, v11 * s, hw, lw);
                *(uint32_t*)&hp[(size_t)(row + 8) * 1024 + cc] = hw;
                *(uint32_t*)&lp[(size_t)(row + 8) * 1024 + cc] = lw;
            } else {
                *(float2*)&C[(size_t)row * N + col]       = make_float2(v00, v01);
                *(float2*)&C[(size_t)(row + 8) * N + col] = make_float2(v10, v11);
            }
        }
    }
}

// ===================== HMMA blocked ring attention =====================
// grid 2048 = (qt:4, blk:16, h:16, b:2); 256 threads (8 warps x 16 q-rows = 128).
__global__ void __launch_bounds__(256)
attn_hmma_kernel(const __nv_bfloat16* __restrict__ Qhi_g, const __nv_bfloat16* __restrict__ Qlo_g,
                 const __nv_bfloat16* __restrict__ Khi_g, const __nv_bfloat16* __restrict__ Klo_g,
                 const __nv_bfloat16* __restrict__ Vthi_g, const __nv_bfloat16* __restrict__ Vtlo_g,
                 __nv_bfloat16* __restrict__ Ahi_o, __nv_bfloat16* __restrict__ Alo_o)
{
    extern __shared__ __align__(16) char dsm[];
    const int tid  = threadIdx.x;
    const int w    = tid >> 5;
    const int lane = tid & 31;
    const int g    = lane >> 2;
    const int t    = lane & 3;

    const int cta = blockIdx.x;
    const int qt  = cta & 3;
    const int blk = (cta >> 2) & 15;
    const int h   = (cta >> 6) & 15;
    const int b   = cta >> 10;
    const size_t rowbase = (size_t)b * 8192;
    const int s0 = blk * 512 + qt * 128;
    const int bh = b * 16 + h;

    // smem: Qhi[128x144] Qlo(+18432); K 2 stages x (hi 9216 + lo 9216); V same
    const uint32_t sQ = smem_u32(dsm);
    const uint32_t sK = sQ + 36864;
    const uint32_t sV = sQ + 73728;

    // ---- Q load: 256 threads x (1 row-half) of 128 rows ----
    {
        const int lr = tid >> 1, lh = tid & 1;
        const __nv_bfloat16* qh = Qhi_g + (rowbase + s0 + lr) * 1024 + h * 64 + lh * 32;
        const __nv_bfloat16* ql = Qlo_g + (rowbase + s0 + lr) * 1024 + h * 64 + lh * 32;
        uint32_t d = sQ + lr * 144 + lh * 64;
        #pragma unroll
        for (int j = 0; j < 4; j++) {
            cp_async16(d + j * 16,         qh + j * 8);
            cp_async16(d + 18432 + j * 16, ql + j * 8);
        }
    }
    auto load_kv = [&](int c) {
        int stage = c & 1;
        int kb2   = (c >= 8) ? ((blk + 1) & 15) : blk;
        int sk    = kb2 * 512 + (c & 7) * 64;
        const int lr = tid >> 2, qtr = tid & 3;   // 64 rows x 4 quarters
        const __nv_bfloat16* kh = Khi_g + (rowbase + sk + lr) * 1024 + h * 64 + qtr * 16;
        const __nv_bfloat16* kl = Klo_g + (rowbase + sk + lr) * 1024 + h * 64 + qtr * 16;
        uint32_t kd = sK + stage * 18432 + lr * 144 + qtr * 32;
        cp_async16(kd,          kh);
        cp_async16(kd + 16,     kh + 8);
        cp_async16(kd + 9216,      kl);
        cp_async16(kd + 9216 + 16, kl + 8);
        const __nv_bfloat16* vh = Vthi_g + ((size_t)bh * 64 + lr) * 8192 + sk + qtr * 16;
        const __nv_bfloat16* vl = Vtlo_g + ((size_t)bh * 64 + lr) * 8192 + sk + qtr * 16;
        uint32_t vd = sV + stage * 18432 + lr * 144 + qtr * 32;
        cp_async16(vd,          vh);
        cp_async16(vd + 16,     vh + 8);
        cp_async16(vd + 9216,      vl);
        cp_async16(vd + 9216 + 16, vl + 8);
        CP_COMMIT();
    };
    load_kv(0);
    load_kv(1);

    float m0 = -1e30f, m1 = -1e30f, l0 = 0.f, l1 = 0.f;
    float oacc[8][4], ofin[8][4];
    #pragma unroll
    for (int nt = 0; nt < 8; nt++)
        #pragma unroll
        for (int j = 0; j < 4; j++) { oacc[nt][j] = 0.f; ofin[nt][j] = 0.f; }

    #pragma unroll 1
    for (int c = 0; c < 16; c++) {
        cp_wait<1>();
        __syncthreads();
        const uint32_t kb = sK + (c & 1) * 18432;
        const uint32_t vb = sV + (c & 1) * 18432;

        // ---- S = Q K^T (m16 x n64, k=64, bf16x3) ----
        float sacc[8][4];
        #pragma unroll
        for (int nt = 0; nt < 8; nt++)
            #pragma unroll
            for (int j = 0; j < 4; j++) sacc[nt][j] = 0.f;

        #pragma unroll
        for (int ks = 0; ks < 4; ks++) {
            uint32_t qa = sQ + (uint32_t)((w * 16 + g) * 144) + ks * 32 + t * 4;
            uint32_t ah[4], al[4];
            ah[0] = lds32(qa);        ah[1] = lds32(qa + 8 * 144);
            ah[2] = lds32(qa + 16);   ah[3] = lds32(qa + 8 * 144 + 16);
            al[0] = lds32(qa + 18432);           al[1] = lds32(qa + 18432 + 8 * 144);
            al[2] = lds32(qa + 18432 + 16);      al[3] = lds32(qa + 18432 + 8 * 144 + 16);
            uint32_t kf[8][2], klf[8][2];
            #pragma unroll
            for (int nt = 0; nt < 8; nt++) {
                uint32_t ka = kb + (uint32_t)((nt * 8 + g) * 144) + ks * 32 + t * 4;
                kf[nt][0]  = lds32(ka);        kf[nt][1]  = lds32(ka + 16);
                klf[nt][0] = lds32(ka + 9216); klf[nt][1] = lds32(ka + 9216 + 16);
            }
            #pragma unroll
            for (int nt = 0; nt < 8; nt++) mma16816(sacc[nt], ah, kf[nt]);
            #pragma unroll
            for (int nt = 0; nt < 8; nt++) mma16816(sacc[nt], ah, klf[nt]);
            #pragma unroll
            for (int nt = 0; nt < 8; nt++) mma16816(sacc[nt], al, kf[nt]);
        }

        // ---- online softmax in exp2 domain ----
        float mx0 = -1e30f, mx1 = -1e30f;
        #pragma unroll
        for (int nt = 0; nt < 8; nt++) {
            mx0 = fmaxf(mx0, fmaxf(sacc[nt][0], sacc[nt][1]));
            mx1 = fmaxf(mx1, fmaxf(sacc[nt][2], sacc[nt][3]));
        }
        mx0 = fmaxf(mx0, __shfl_xor_sync(0xffffffffu, mx0, 1));
        mx0 = fmaxf(mx0, __shfl_xor_sync(0xffffffffu, mx0, 2));
        mx1 = fmaxf(mx1, __shfl_xor_sync(0xffffffffu, mx1, 1));
        mx1 = fmaxf(mx1, __shfl_xor_sync(0xffffffffu, mx1, 2));
        float mn0 = fmaxf(m0, mx0), mn1 = fmaxf(m1, mx1);
        float alpha0 = ex2f(m0 - mn0), alpha1 = ex2f(m1 - mn1);
        float rs0 = 0.f, rs1 = 0.f;
        #pragma unroll
        for (int nt = 0; nt < 8; nt++) {
            sacc[nt][0] = ex2f(sacc[nt][0] - mn0);
            sacc[nt][1] = ex2f(sacc[nt][1] - mn0);
            sacc[nt][2] = ex2f(sacc[nt][2] - mn1);
            sacc[nt][3] = ex2f(sacc[nt][3] - mn1);
            rs0 += sacc[nt][0] + sacc[nt][1];
            rs1 += sacc[nt][2] + sacc[nt][3];
        }
        rs0 += __shfl_xor_sync(0xffffffffu, rs0, 1);
        rs0 += __shfl_xor_sync(0xffffffffu, rs0, 2);
        rs1 += __shfl_xor_sync(0xffffffffu, rs1, 1);
        rs1 += __shfl_xor_sync(0xffffffffu, rs1, 2);
        l0 = l0 * alpha0 + rs0;
        l1 = l1 * alpha1 + rs1;
        m0 = mn0; m1 = mn1;
        #pragma unroll
        for (int nt = 0; nt < 8; nt++) {
            oacc[nt][0] *= alpha0; oacc[nt][1] *= alpha0;
            oacc[nt][2] *= alpha1; oacc[nt][3] *= alpha1;
        }

        // ---- O += P V (P hi/lo built in registers) ----
        #pragma unroll
        for (int ks = 0; ks < 4; ks++) {
            uint32_t pA[4], pL[4];
            #pragma unroll
            for (int half = 0; half < 2; half++) {
                const float* s2 = sacc[2 * ks + half];
                uint32_t h01, l01, h23, l23;
                split2(s2[0], s2[1], h01, l01);
                split2(s2[2], s2[3], h23, l23);
                pA[2 * half]     = h01;
                pA[2 * half + 1] = h23;
                pL[2 * half]     = l01;
                pL[2 * half + 1] = l23;
            }
            uint32_t vf[8][2], vlf[8][2];
            #pragma unroll
            for (int nt = 0; nt < 8; nt++) {
                uint32_t va = vb + (uint32_t)((nt * 8 + g) * 144) + ks * 32 + t * 4;
                vf[nt][0]  = lds32(va);        vf[nt][1]  = lds32(va + 16);
                vlf[nt][0] = lds32(va + 9216); vlf[nt][1] = lds32(va + 9216 + 16);
            }
            #pragma unroll
            for (int nt = 0; nt < 8; nt++) mma16816(oacc[nt], pA, vf[nt]);
            #pragma unroll
            for (int nt = 0; nt < 8; nt++) mma16816(oacc[nt], pA, vlf[nt]);
            #pragma unroll
            for (int nt = 0; nt < 8; nt++) mma16816(oacc[nt], pL, vf[nt]);
        }

        __syncthreads();
        if (c < 14) load_kv(c + 2);

        if ((c & 7) == 7) {
            float i0 = 1.0f / l0, i1 = 1.0f / l1;
            #pragma unroll
            for (int nt = 0; nt < 8; nt++) {
                ofin[nt][0] += oacc[nt][0] * i0;
                ofin[nt][1] += oacc[nt][1] * i0;
                ofin[nt][2] += oacc[nt][2] * i1;
                ofin[nt][3] += oacc[nt][3] * i1;
                oacc[nt][0] = oacc[nt][1] = oacc[nt][2] = oacc[nt][3] = 0.f;
            }
            m0 = m1 = -1e30f;
            l0 = l1 = 0.f;
        }
    }

    // ---- store O as bf16 hi/lo (feeds gemm2 directly) ----
    size_t r0 = rowbase + s0 + w * 16 + g;
    #pragma unroll
    for (int nt = 0; nt < 8; nt++) {
        int col = h * 64 + nt * 8 + t * 2;
        uint32_t hw, lw;
        split2(ofin[nt][0], ofin[nt][1], hw, lw);
        *(uint32_t*)&Ahi_o[r0 * 1024 + col] = hw;
        *(uint32_t*)&Alo_o[r0 * 1024 + col] = lw;
        split2(ofin[nt][2], ofin[nt][3], hw, lw);
        *(uint32_t*)&Ahi_o[(r0 + 8) * 1024 + col] = hw;
        *(uint32_t*)&Alo_o[(r0 + 8) * 1024 + col] = lw;
    }
}

// ============================ launcher ===================================
extern "C" void kernel_launch(void* const* d_in, const int* in_sizes, int n_in,
                              void* d_out, int out_size)
{
    const float* x    = (const float*)d_in[0];
    const float* Wqkv = (const float*)d_in[1];
    const float* bqkv = (const float*)d_in[2];
    const float* Wout = (const float*)d_in[3];
    const float* bout = (const float*)d_in[4];
    float* out = (float*)d_out;

    float* qkv; cudaGetSymbolAddress((void**)&qkv, g_qkv);
    __nv_bfloat16 *xhi, *xlo, *whi, *wlo, *ahi, *alo, *ohi, *olo;
    __nv_bfloat16 *qhi, *qlo, *khi, *klo, *vthi, *vtlo;
    cudaGetSymbolAddress((void**)&xhi, g_xhi);  cudaGetSymbolAddress((void**)&xlo, g_xlo);
    cudaGetSymbolAddress((void**)&whi, g_whi);  cudaGetSymbolAddress((void**)&wlo, g_wlo);
    cudaGetSymbolAddress((void**)&ahi, g_ahi);  cudaGetSymbolAddress((void**)&alo, g_alo);
    cudaGetSymbolAddress((void**)&ohi, g_ohi);  cudaGetSymbolAddress((void**)&olo, g_olo);
    cudaGetSymbolAddress((void**)&qhi, g_qhi);  cudaGetSymbolAddress((void**)&qlo, g_qlo);
    cudaGetSymbolAddress((void**)&khi, g_khi);  cudaGetSymbolAddress((void**)&klo, g_klo);
    cudaGetSymbolAddress((void**)&vthi, g_vthi); cudaGetSymbolAddress((void**)&vtlo, g_vtlo);

    const int gemm_smem = 2 * 40960;   // 81920 B -> 2 CTAs/SM
    cudaFuncSetAttribute(gemm_hmma_kernel, cudaFuncAttributeMaxDynamicSharedMemorySize,
                         gemm_smem);
    const int attn_smem = 110592;      // Q(hi/lo) + 2-stage K(hi/lo) + 2-stage Vt(hi/lo)
    cudaFuncSetAttribute(attn_hmma_kernel, cudaFuncAttributeMaxDynamicSharedMemorySize,
                         attn_smem);

    // 0) operand conversion for gemm1
    split_kernel<<<16384, 256>>>(x, xhi, xlo);
    transpose_split_kernel<<<dim3(3072 / 32, 1024 / 32), dim3(32, 8)>>>(
        Wqkv, whi, wlo, 1024, 3072);
    transpose_split_kernel<<<dim3(1024 / 32, 1024 / 32), dim3(32, 8)>>>(
        Wout, ohi, olo, 1024, 1024);

    // 1) qkv = x @ W_qkv + b_qkv; q/k emitted as bf16 hi/lo, v as fp32
    gemm_hmma_kernel<<<dim3(3072 / 128, 16384 / 128), 256, gemm_smem>>>(
        xhi, xlo, whi, wlo, bqkv, qkv, 3072, 1, qhi, qlo, khi, klo);

    // 2) v transpose/split
    v_transpose_split_kernel<<<dim3(256, 2, 32), dim3(32, 8)>>>(qkv, vthi, vtlo);

    // 3) blocked ring attention (HMMA) -> ahi/alo
    attn_hmma_kernel<<<2048, 256, attn_smem>>>(qhi, qlo, khi, klo, vthi, vtlo, ahi, alo);

    // 4) out = att @ W_out + b_out
    gemm_hmma_kernel<<<dim3(1024 / 128, 16384 / 128), 256, gemm_smem>>>(
        ahi, alo, ohi, olo, bout, out, 1024, 0, nullptr, nullptr, nullptr, nullptr);
}

// round 7
// speedup vs baseline: 2.2093x; 1.0126x over previous
#include <cuda_runtime.h>
#include <cuda_bf16.h>
#include <cstdint>

typedef unsigned long long ull;

// ===================== PTX helpers (baseline, compute_103-safe) ==========
__device__ __forceinline__ uint32_t smem_u32(const void* p) {
    uint32_t a;
    asm("{ .reg .u64 t; cvta.to.shared.u64 t, %1; cvt.u32.u64 %0, t; }"
        : "=r"(a) : "l"(p));
    return a;
}
__device__ __forceinline__ void cp_async16(uint32_t dst, const void* src) {
    asm volatile("cp.async.cg.shared.global [%0], [%1], 16;" :: "r"(dst), "l"(src));
}
#define CP_COMMIT() asm volatile("cp.async.commit_group;" ::: "memory")
template <int N>
__device__ __forceinline__ void cp_wait() {
    asm volatile("cp.async.wait_group %0;" :: "n"(N) : "memory");
}
__device__ __forceinline__ uint32_t lds32(uint32_t a) {
    uint32_t v;
    asm volatile("ld.shared.b32 %0, [%1];" : "=r"(v) : "r"(a));
    return v;
}
// mma.sync m16n8k16 row.col bf16 -> f32
__device__ __forceinline__ void mma16816(float* d, const uint32_t* a, const uint32_t* b) {
    asm volatile(
        "mma.sync.aligned.m16n8k16.row.col.f32.bf16.bf16.f32 "
        "{%0,%1,%2,%3}, {%4,%5,%6,%7}, {%8,%9}, {%0,%1,%2,%3};"
        : "+f"(d[0]), "+f"(d[1]), "+f"(d[2]), "+f"(d[3])
        : "r"(a[0]), "r"(a[1]), "r"(a[2]), "r"(a[3]), "r"(b[0]), "r"(b[1]));
}
__device__ __forceinline__ float ex2f(float x) {
    float y; asm("ex2.approx.f32 %0, %1;" : "=f"(y) : "f"(x)); return y;
}
// pack two f32 -> bf16x2 (second operand lands in the LOW half)
__device__ __forceinline__ uint32_t cvt_bf16x2(float hi, float lo) {
    uint32_t r;
    asm("cvt.rn.bf16x2.f32 %0, %1, %2;" : "=r"(r) : "f"(hi), "f"(lo));
    return r;
}
// split two fp32 into bf16x2 hi-word + bf16x2 residual-word
__device__ __forceinline__ void split2(float v0, float v1, uint32_t& hw, uint32_t& lw) {
    hw = cvt_bf16x2(v1, v0);
    float f0 = __uint_as_float(hw << 16);
    float f1 = __uint_as_float(hw & 0xffff0000u);
    lw = cvt_bf16x2(v1 - f1, v0 - f0);
}

// ---------------- scratch (allocation-free rule: device globals) --------
__device__ float g_qkv[(size_t)16384 * 3072];          // fp32 (v cols used)
__device__ __nv_bfloat16 g_xhi[(size_t)16384 * 1024];
__device__ __nv_bfloat16 g_xlo[(size_t)16384 * 1024];
__device__ __nv_bfloat16 g_whi[(size_t)3072 * 1024];   // W_qkv^T split
__device__ __nv_bfloat16 g_wlo[(size_t)3072 * 1024];
__device__ __nv_bfloat16 g_ahi[(size_t)16384 * 1024];  // attention out split
__device__ __nv_bfloat16 g_alo[(size_t)16384 * 1024];
__device__ __nv_bfloat16 g_ohi[(size_t)1024 * 1024];   // W_out^T split
__device__ __nv_bfloat16 g_olo[(size_t)1024 * 1024];
__device__ __nv_bfloat16 g_qhi[(size_t)16384 * 1024];  // scaled by 0.125*log2e
__device__ __nv_bfloat16 g_qlo[(size_t)16384 * 1024];
__device__ __nv_bfloat16 g_khi[(size_t)16384 * 1024];
__device__ __nv_bfloat16 g_klo[(size_t)16384 * 1024];
__device__ __nv_bfloat16 g_vthi[(size_t)2 * 16 * 64 * 8192];  // [b][h][d][s]
__device__ __nv_bfloat16 g_vtlo[(size_t)2 * 16 * 64 * 8192];

// ===================== conversion kernels =====================
__global__ void __launch_bounds__(256)
split_kernel(const float* __restrict__ src, __nv_bfloat16* __restrict__ hi,
             __nv_bfloat16* __restrict__ lo)
{
    size_t i = ((size_t)blockIdx.x * 256 + threadIdx.x) * 4;
    float4 v = *(const float4*)(src + i);
    uint32_t h0, l0w, h1, l1w;
    split2(v.x, v.y, h0, l0w);
    split2(v.z, v.w, h1, l1w);
    ((uint32_t*)(hi + i))[0] = h0; ((uint32_t*)(hi + i))[1] = h1;
    ((uint32_t*)(lo + i))[0] = l0w; ((uint32_t*)(lo + i))[1] = l1w;
}

// W [K,N] fp32 -> W^T [N,K] bf16 hi/lo
__global__ void __launch_bounds__(256)
transpose_split_kernel(const float* __restrict__ W, __nv_bfloat16* __restrict__ hiT,
                       __nv_bfloat16* __restrict__ loT, int K, int N)
{
    __shared__ float t[32][33];
    int n0 = blockIdx.x * 32, k0 = blockIdx.y * 32;
    int tx = threadIdx.x, ty = threadIdx.y;
    #pragma unroll
    for (int i = 0; i < 4; i++)
        t[ty + 8 * i][tx] = W[(size_t)(k0 + ty + 8 * i) * N + n0 + tx];
    __syncthreads();
    #pragma unroll
    for (int i = 0; i < 4; i++) {
        float v = t[tx][ty + 8 * i];
        __nv_bfloat16 h = __float2bfloat16(v);
        size_t o = (size_t)(n0 + ty + 8 * i) * K + k0 + tx;
        hiT[o] = h;
        loT[o] = __float2bfloat16(v - __bfloat162float(h));
    }
}

// v columns of qkv -> per-head transpose [b][h][d][s], split bf16
__global__ void __launch_bounds__(256)
v_transpose_split_kernel(const float* __restrict__ qkv,
                         __nv_bfloat16* __restrict__ vthi,
                         __nv_bfloat16* __restrict__ vtlo)
{
    __shared__ float tbuf[32][33];
    int bh = blockIdx.z;
    int b = bh >> 4, h = bh & 15;
    int s0 = blockIdx.x * 32, d0 = blockIdx.y * 32;
    int tx = threadIdx.x, ty = threadIdx.y;   // 32 x 8
    #pragma unroll
    for (int i = 0; i < 4; i++)
        tbuf[ty + 8 * i][tx] =
            qkv[((size_t)b * 8192 + s0 + ty + 8 * i) * 3072 + 2048 + h * 64 + d0 + tx];
    __syncthreads();
    #pragma unroll
    for (int i = 0; i < 4; i++) {
        float v = tbuf[tx][ty + 8 * i];       // s = s0+tx, d = d0+ty+8i
        size_t o = ((size_t)bh * 64 + d0 + ty + 8 * i) * 8192 + s0 + tx;
        __nv_bfloat16 hv = __float2bfloat16(v);
        vthi[o] = hv;
        vtlo[o] = __float2bfloat16(v - __bfloat162float(hv));
    }
}

// ===================== HMMA bf16x3 GEMM ======================
// 128 threads, 4 warps in 2x2, warp tile 64x64 (24 MAC/byte smem->RF).
// CTA tile 128x128, k-chunk 32, 2-stage pipeline, 2 CTAs/SM.
#define OP_BYTES   10240u
#define STG_BYTES  40960u

__global__ void __launch_bounds__(128)
gemm_hmma_kernel(const __nv_bfloat16* __restrict__ Ahi, const __nv_bfloat16* __restrict__ Alo,
                 const __nv_bfloat16* __restrict__ Bhi, const __nv_bfloat16* __restrict__ Blo,
                 const float* __restrict__ bias, float* __restrict__ C, int N, int mode,
                 __nv_bfloat16* __restrict__ qhi, __nv_bfloat16* __restrict__ qlo,
                 __nv_bfloat16* __restrict__ khi, __nv_bfloat16* __restrict__ klo)
{
    extern __shared__ __align__(16) char dsm[];
    const int tid  = threadIdx.x;
    const int wid  = tid >> 5;
    const int lane = tid & 31;
    const int g    = lane >> 2;
    const int tig  = lane & 3;
    const int wm   = wid & 1;      // 2 warps along M (64 rows each)
    const int wn   = wid >> 1;     // 2 warps along N (64 cols each)
    const int m0 = blockIdx.y * 128;
    const int n0 = blockIdx.x * 128;

    const uint32_t sbase = smem_u32(dsm);

    // load slots: per operand 512 (row,unit) 16B slots; 4 per thread
    int rowi[4], uni[4];
    #pragma unroll
    for (int i = 0; i < 4; i++) {
        int lin = tid + 128 * i;
        rowi[i] = lin >> 2;
        uni[i]  = lin & 3;
    }

    auto load_chunk = [&](int c) {
        uint32_t sb = sbase + (uint32_t)(c & 1) * STG_BYTES;
        int kof = c * 32;
        #pragma unroll
        for (int i = 0; i < 4; i++) {
            int r = rowi[i], u = uni[i];
            uint32_t so = (uint32_t)(r * 80 + u * 16);
            size_t ga = (size_t)(m0 + r) * 1024 + kof + u * 8;
            size_t gb = (size_t)(n0 + r) * 1024 + kof + u * 8;
            cp_async16(sb + so,                 Ahi + ga);
            cp_async16(sb + OP_BYTES + so,      Alo + ga);
            cp_async16(sb + 2 * OP_BYTES + so,  Bhi + gb);
            cp_async16(sb + 3 * OP_BYTES + so,  Blo + gb);
        }
        CP_COMMIT();
    };

    load_chunk(0); load_chunk(1);

    float acc[4][8][4];
    #pragma unroll
    for (int mt = 0; mt < 4; mt++)
        #pragma unroll
        for (int nt = 0; nt < 8; nt++)
            #pragma unroll
            for (int r = 0; r < 4; r++) acc[mt][nt][r] = 0.f;

    #pragma unroll 1
    for (int c = 0; c < 32; c++) {
        if (c < 31) cp_wait<1>();
        else        cp_wait<0>();
        __syncthreads();

        uint32_t sb = sbase + (uint32_t)(c & 1) * STG_BYTES;
        #pragma unroll
        for (int kh = 0; kh < 2; kh++) {
            const uint32_t kb = kh * 32 + tig * 4;
            uint32_t ah[4][4], al[4][4];
            #pragma unroll
            for (int mt = 0; mt < 4; mt++) {
                uint32_t r0 = sb + (uint32_t)((wm * 64 + mt * 16 + g) * 80) + kb;
                uint32_t r1 = r0 + 8 * 80;
                ah[mt][0] = lds32(r0);      ah[mt][1] = lds32(r1);
                ah[mt][2] = lds32(r0 + 16); ah[mt][3] = lds32(r1 + 16);
                al[mt][0] = lds32(r0 + OP_BYTES);      al[mt][1] = lds32(r1 + OP_BYTES);
                al[mt][2] = lds32(r0 + OP_BYTES + 16); al[mt][3] = lds32(r1 + OP_BYTES + 16);
            }
            // two nt-halves to cap register pressure
            #pragma unroll
            for (int nh = 0; nh < 2; nh++) {
                uint32_t bh[4][2], bl[4][2];
                #pragma unroll
                for (int ntl = 0; ntl < 4; ntl++) {
                    int nt = nh * 4 + ntl;
                    uint32_t rb = sb + 2 * OP_BYTES +
                                  (uint32_t)((wn * 64 + nt * 8 + g) * 80) + kb;
                    bh[ntl][0] = lds32(rb);      bh[ntl][1] = lds32(rb + 16);
                    bl[ntl][0] = lds32(rb + OP_BYTES);
                    bl[ntl][1] = lds32(rb + OP_BYTES + 16);
                }
                #pragma unroll
                for (int mt = 0; mt < 4; mt++)
                    #pragma unroll
                    for (int ntl = 0; ntl < 4; ntl++)
                        mma16816(acc[mt][nh * 4 + ntl], ah[mt], bh[ntl]);
                #pragma unroll
                for (int mt = 0; mt < 4; mt++)
                    #pragma unroll
                    for (int ntl = 0; ntl < 4; ntl++)
                        mma16816(acc[mt][nh * 4 + ntl], ah[mt], bl[ntl]);
                #pragma unroll
                for (int mt = 0; mt < 4; mt++)
                    #pragma unroll
                    for (int ntl = 0; ntl < 4; ntl++)
                        mma16816(acc[mt][nh * 4 + ntl], al[mt], bh[ntl]);
            }
        }
        __syncthreads();
        if (c < 30) load_chunk(c + 2);
    }

    const float qsc = 0.18033688011112042f;   // (1/8)*log2(e)
    #pragma unroll
    for (int mt = 0; mt < 4; mt++) {
        int row = m0 + wm * 64 + mt * 16 + g;
        #pragma unroll
        for (int nt = 0; nt < 8; nt++) {
            int col = n0 + wn * 64 + nt * 8 + tig * 2;
            float b0 = bias[col], b1 = bias[col + 1];
            float v00 = acc[mt][nt][0] + b0, v01 = acc[mt][nt][1] + b1;
            float v10 = acc[mt][nt][2] + b0, v11 = acc[mt][nt][3] + b1;
            if (mode == 1 && col < 2048) {
                bool isq = col < 1024;
                float s = isq ? qsc : 1.f;
                __nv_bfloat16* hp = isq ? qhi : khi;
                __nv_bfloat16* lp = isq ? qlo : klo;
                int cc = col & 1023;
                uint32_t hw, lw;
                split2(v00 * s, v01 * s, hw, lw);
                *(uint32_t*)&hp[(size_t)row * 1024 + cc] = hw;
                *(uint32_t*)&lp[(size_t)row * 1024 + cc] = lw;
                split2(v10 * s, v11 * s, hw, lw);
                *(uint32_t*)&hp[(size_t)(row + 8) * 1024 + cc] = hw;
                *(uint32_t*)&lp[(size_t)(row + 8) * 1024 + cc] = lw;
            } else {
                *(float2*)&C[(size_t)row * N + col]       = make_float2(v00, v01);
                *(float2*)&C[(size_t)(row + 8) * N + col] = make_float2(v10, v11);
            }
        }
    }
}

// ===================== HMMA blocked ring attention =====================
// grid 2048 = (qt:4, blk:16, h:16, b:2); 256 threads (8 warps x 16 q-rows = 128).
__global__ void __launch_bounds__(256)
attn_hmma_kernel(const __nv_bfloat16* __restrict__ Qhi_g, const __nv_bfloat16* __restrict__ Qlo_g,
                 const __nv_bfloat16* __restrict__ Khi_g, const __nv_bfloat16* __restrict__ Klo_g,
                 const __nv_bfloat16* __restrict__ Vthi_g, const __nv_bfloat16* __restrict__ Vtlo_g,
                 __nv_bfloat16* __restrict__ Ahi_o, __nv_bfloat16* __restrict__ Alo_o)
{
    extern __shared__ __align__(16) char dsm[];
    const int tid  = threadIdx.x;
    const int w    = tid >> 5;
    const int lane = tid & 31;
    const int g    = lane >> 2;
    const int t    = lane & 3;

    const int cta = blockIdx.x;
    const int qt  = cta & 3;
    const int blk = (cta >> 2) & 15;
    const int h   = (cta >> 6) & 15;
    const int b   = cta >> 10;
    const size_t rowbase = (size_t)b * 8192;
    const int s0 = blk * 512 + qt * 128;
    const int bh = b * 16 + h;

    // smem: Qhi[128x144] Qlo(+18432); K 2 stages x (hi 9216 + lo 9216); V same
    const uint32_t sQ = smem_u32(dsm);
    const uint32_t sK = sQ + 36864;
    const uint32_t sV = sQ + 73728;

    // ---- Q load: 256 threads x (1 row-half) of 128 rows ----
    {
        const int lr = tid >> 1, lh = tid & 1;
        const __nv_bfloat16* qh = Qhi_g + (rowbase + s0 + lr) * 1024 + h * 64 + lh * 32;
        const __nv_bfloat16* ql = Qlo_g + (rowbase + s0 + lr) * 1024 + h * 64 + lh * 32;
        uint32_t d = sQ + lr * 144 + lh * 64;
        #pragma unroll
        for (int j = 0; j < 4; j++) {
            cp_async16(d + j * 16,         qh + j * 8);
            cp_async16(d + 18432 + j * 16, ql + j * 8);
        }
    }
    auto load_kv = [&](int c) {
        int stage = c & 1;
        int kb2   = (c >= 8) ? ((blk + 1) & 15) : blk;
        int sk    = kb2 * 512 + (c & 7) * 64;
        const int lr = tid >> 2, qtr = tid & 3;   // 64 rows x 4 quarters
        const __nv_bfloat16* kh = Khi_g + (rowbase + sk + lr) * 1024 + h * 64 + qtr * 16;
        const __nv_bfloat16* kl = Klo_g + (rowbase + sk + lr) * 1024 + h * 64 + qtr * 16;
        uint32_t kd = sK + stage * 18432 + lr * 144 + qtr * 32;
        cp_async16(kd,          kh);
        cp_async16(kd + 16,     kh + 8);
        cp_async16(kd + 9216,      kl);
        cp_async16(kd + 9216 + 16, kl + 8);
        const __nv_bfloat16* vh = Vthi_g + ((size_t)bh * 64 + lr) * 8192 + sk + qtr * 16;
        const __nv_bfloat16* vl = Vtlo_g + ((size_t)bh * 64 + lr) * 8192 + sk + qtr * 16;
        uint32_t vd = sV + stage * 18432 + lr * 144 + qtr * 32;
        cp_async16(vd,          vh);
        cp_async16(vd + 16,     vh + 8);
        cp_async16(vd + 9216,      vl);
        cp_async16(vd + 9216 + 16, vl + 8);
        CP_COMMIT();
    };
    load_kv(0);
    load_kv(1);

    float m0 = -1e30f, m1 = -1e30f, l0 = 0.f, l1 = 0.f;
    float oacc[8][4], ofin[8][4];
    #pragma unroll
    for (int nt = 0; nt < 8; nt++)
        #pragma unroll
        for (int j = 0; j < 4; j++) { oacc[nt][j] = 0.f; ofin[nt][j] = 0.f; }

    #pragma unroll 1
    for (int c = 0; c < 16; c++) {
        cp_wait<1>();
        __syncthreads();
        const uint32_t kb = sK + (c & 1) * 18432;
        const uint32_t vb = sV + (c & 1) * 18432;

        // ---- S = Q K^T (m16 x n64, k=64, bf16x3) ----
        float sacc[8][4];
        #pragma unroll
        for (int nt = 0; nt < 8; nt++)
            #pragma unroll
            for (int j = 0; j < 4; j++) sacc[nt][j] = 0.f;

        #pragma unroll
        for (int ks = 0; ks < 4; ks++) {
            uint32_t qa = sQ + (uint32_t)((w * 16 + g) * 144) + ks * 32 + t * 4;
            uint32_t ah[4], al[4];
            ah[0] = lds32(qa);        ah[1] = lds32(qa + 8 * 144);
            ah[2] = lds32(qa + 16);   ah[3] = lds32(qa + 8 * 144 + 16);
            al[0] = lds32(qa + 18432);           al[1] = lds32(qa + 18432 + 8 * 144);
            al[2] = lds32(qa + 18432 + 16);      al[3] = lds32(qa + 18432 + 8 * 144 + 16);
            uint32_t kf[8][2], klf[8][2];
            #pragma unroll
            for (int nt = 0; nt < 8; nt++) {
                uint32_t ka = kb + (uint32_t)((nt * 8 + g) * 144) + ks * 32 + t * 4;
                kf[nt][0]  = lds32(ka);        kf[nt][1]  = lds32(ka + 16);
                klf[nt][0] = lds32(ka + 9216); klf[nt][1] = lds32(ka + 9216 + 16);
            }
            #pragma unroll
            for (int nt = 0; nt < 8; nt++) mma16816(sacc[nt], ah, kf[nt]);
            #pragma unroll
            for (int nt = 0; nt < 8; nt++) mma16816(sacc[nt], ah, klf[nt]);
            #pragma unroll
            for (int nt = 0; nt < 8; nt++) mma16816(sacc[nt], al, kf[nt]);
        }

        // ---- online softmax in exp2 domain ----
        float mx0 = -1e30f, mx1 = -1e30f;
        #pragma unroll
        for (int nt = 0; nt < 8; nt++) {
            mx0 = fmaxf(mx0, fmaxf(sacc[nt][0], sacc[nt][1]));
            mx1 = fmaxf(mx1, fmaxf(sacc[nt][2], sacc[nt][3]));
        }
        mx0 = fmaxf(mx0, __shfl_xor_sync(0xffffffffu, mx0, 1));
        mx0 = fmaxf(mx0, __shfl_xor_sync(0xffffffffu, mx0, 2));
        mx1 = fmaxf(mx1, __shfl_xor_sync(0xffffffffu, mx1, 1));
        mx1 = fmaxf(mx1, __shfl_xor_sync(0xffffffffu, mx1, 2));
        float mn0 = fmaxf(m0, mx0), mn1 = fmaxf(m1, mx1);
        float alpha0 = ex2f(m0 - mn0), alpha1 = ex2f(m1 - mn1);
        float rs0 = 0.f, rs1 = 0.f;
        #pragma unroll
        for (int nt = 0; nt < 8; nt++) {
            sacc[nt][0] = ex2f(sacc[nt][0] - mn0);
            sacc[nt][1] = ex2f(sacc[nt][1] - mn0);
            sacc[nt][2] = ex2f(sacc[nt][2] - mn1);
            sacc[nt][3] = ex2f(sacc[nt][3] - mn1);
            rs0 += sacc[nt][0] + sacc[nt][1];
            rs1 += sacc[nt][2] + sacc[nt][3];
        }
        rs0 += __shfl_xor_sync(0xffffffffu, rs0, 1);
        rs0 += __shfl_xor_sync(0xffffffffu, rs0, 2);
        rs1 += __shfl_xor_sync(0xffffffffu, rs1, 1);
        rs1 += __shfl_xor_sync(0xffffffffu, rs1, 2);
        l0 = l0 * alpha0 + rs0;
        l1 = l1 * alpha1 + rs1;
        m0 = mn0; m1 = mn1;
        #pragma unroll
        for (int nt = 0; nt < 8; nt++) {
            oacc[nt][0] *= alpha0; oacc[nt][1] *= alpha0;
            oacc[nt][2] *= alpha1; oacc[nt][3] *= alpha1;
        }

        // ---- O += P V (P hi/lo built in registers) ----
        #pragma unroll
        for (int ks = 0; ks < 4; ks++) {
            uint32_t pA[4], pL[4];
            #pragma unroll
            for (int half = 0; half < 2; half++) {
                const float* s2 = sacc[2 * ks + half];
                uint32_t h01, l01, h23, l23;
                split2(s2[0], s2[1], h01, l01);
                split2(s2[2], s2[3], h23, l23);
                pA[2 * half]     = h01;
                pA[2 * half + 1] = h23;
                pL[2 * half]     = l01;
                pL[2 * half + 1] = l23;
            }
            uint32_t vf[8][2], vlf[8][2];
            #pragma unroll
            for (int nt = 0; nt < 8; nt++) {
                uint32_t va = vb + (uint32_t)((nt * 8 + g) * 144) + ks * 32 + t * 4;
                vf[nt][0]  = lds32(va);        vf[nt][1]  = lds32(va + 16);
                vlf[nt][0] = lds32(va + 9216); vlf[nt][1] = lds32(va + 9216 + 16);
            }
            #pragma unroll
            for (int nt = 0; nt < 8; nt++) mma16816(oacc[nt], pA, vf[nt]);
            #pragma unroll
            for (int nt = 0; nt < 8; nt++) mma16816(oacc[nt], pA, vlf[nt]);
            #pragma unroll
            for (int nt = 0; nt < 8; nt++) mma16816(oacc[nt], pL, vf[nt]);
        }

        __syncthreads();
        if (c < 14) load_kv(c + 2);

        if ((c & 7) == 7) {
            float i0 = 1.0f / l0, i1 = 1.0f / l1;
            #pragma unroll
            for (int nt = 0; nt < 8; nt++) {
                ofin[nt][0] += oacc[nt][0] * i0;
                ofin[nt][1] += oacc[nt][1] * i0;
                ofin[nt][2] += oacc[nt][2] * i1;
                ofin[nt][3] += oacc[nt][3] * i1;
                oacc[nt][0] = oacc[nt][1] = oacc[nt][2] = oacc[nt][3] = 0.f;
            }
            m0 = m1 = -1e30f;
            l0 = l1 = 0.f;
        }
    }

    // ---- store O as bf16 hi/lo (feeds gemm2 directly) ----
    size_t r0 = rowbase + s0 + w * 16 + g;
    #pragma unroll
    for (int nt = 0; nt < 8; nt++) {
        int col = h * 64 + nt * 8 + t * 2;
        uint32_t hw, lw;
        split2(ofin[nt][0], ofin[nt][1], hw, lw);
        *(uint32_t*)&Ahi_o[r0 * 1024 + col] = hw;
        *(uint32_t*)&Alo_o[r0 * 1024 + col] = lw;
        split2(ofin[nt][2], ofin[nt][3], hw, lw);
        *(uint32_t*)&Ahi_o[(r0 + 8) * 1024 + col] = hw;
        *(uint32_t*)&Alo_o[(r0 + 8) * 1024 + col] = lw;
    }
}

// ============================ launcher ===================================
extern "C" void kernel_launch(void* const* d_in, const int* in_sizes, int n_in,
                              void* d_out, int out_size)
{
    const float* x    = (const float*)d_in[0];
    const float* Wqkv = (const float*)d_in[1];
    const float* bqkv = (const float*)d_in[2];
    const float* Wout = (const float*)d_in[3];
    const float* bout = (const float*)d_in[4];
    float* out = (float*)d_out;

    float* qkv; cudaGetSymbolAddress((void**)&qkv, g_qkv);
    __nv_bfloat16 *xhi, *xlo, *whi, *wlo, *ahi, *alo, *ohi, *olo;
    __nv_bfloat16 *qhi, *qlo, *khi, *klo, *vthi, *vtlo;
    cudaGetSymbolAddress((void**)&xhi, g_xhi);  cudaGetSymbolAddress((void**)&xlo, g_xlo);
    cudaGetSymbolAddress((void**)&whi, g_whi);  cudaGetSymbolAddress((void**)&wlo, g_wlo);
    cudaGetSymbolAddress((void**)&ahi, g_ahi);  cudaGetSymbolAddress((void**)&alo, g_alo);
    cudaGetSymbolAddress((void**)&ohi, g_ohi);  cudaGetSymbolAddress((void**)&olo, g_olo);
    cudaGetSymbolAddress((void**)&qhi, g_qhi);  cudaGetSymbolAddress((void**)&qlo, g_qlo);
    cudaGetSymbolAddress((void**)&khi, g_khi);  cudaGetSymbolAddress((void**)&klo, g_klo);
    cudaGetSymbolAddress((void**)&vthi, g_vthi); cudaGetSymbolAddress((void**)&vtlo, g_vtlo);

    const int gemm_smem = 2 * 40960;   // 81920 B -> 2 CTAs/SM
    cudaFuncSetAttribute(gemm_hmma_kernel, cudaFuncAttributeMaxDynamicSharedMemorySize,
                         gemm_smem);
    const int attn_smem = 110592;
    cudaFuncSetAttribute(attn_hmma_kernel, cudaFuncAttributeMaxDynamicSharedMemorySize,
                         attn_smem);

    // 0) operand conversion for gemm1
    split_kernel<<<16384, 256>>>(x, xhi, xlo);
    transpose_split_kernel<<<dim3(3072 / 32, 1024 / 32), dim3(32, 8)>>>(
        Wqkv, whi, wlo, 1024, 3072);
    transpose_split_kernel<<<dim3(1024 / 32, 1024 / 32), dim3(32, 8)>>>(
        Wout, ohi, olo, 1024, 1024);

    // 1) qkv = x @ W_qkv + b_qkv; q/k emitted as bf16 hi/lo, v as fp32
    gemm_hmma_kernel<<<dim3(3072 / 128, 16384 / 128), 128, gemm_smem>>>(
        xhi, xlo, whi, wlo, bqkv, qkv, 3072, 1, qhi, qlo, khi, klo);

    // 2) v transpose/split
    v_transpose_split_kernel<<<dim3(256, 2, 32), dim3(32, 8)>>>(qkv, vthi, vtlo);

    // 3) blocked ring attention (HMMA) -> ahi/alo
    attn_hmma_kernel<<<2048, 256, attn_smem>>>(qhi, qlo, khi, klo, vthi, vtlo, ahi, alo);

    // 4) out = att @ W_out + b_out
    gemm_hmma_kernel<<<dim3(1024 / 128, 16384 / 128), 128, gemm_smem>>>(
        ahi, alo, ohi, olo, bout, out, 1024, 0, nullptr, nullptr, nullptr, nullptr);
}

// round 8
// speedup vs baseline: 2.3134x; 1.0471x over previous
#include <cuda_runtime.h>
#include <cuda_bf16.h>
#include <cstdint>

typedef unsigned long long ull;

// ===================== PTX helpers (baseline, compute_103-safe) ==========
__device__ __forceinline__ uint32_t smem_u32(const void* p) {
    uint32_t a;
    asm("{ .reg .u64 t; cvta.to.shared.u64 t, %1; cvt.u32.u64 %0, t; }"
        : "=r"(a) : "l"(p));
    return a;
}
__device__ __forceinline__ void cp_async16(uint32_t dst, const void* src) {
    asm volatile("cp.async.cg.shared.global [%0], [%1], 16;" :: "r"(dst), "l"(src));
}
#define CP_COMMIT() asm volatile("cp.async.commit_group;" ::: "memory")
template <int N>
__device__ __forceinline__ void cp_wait() {
    asm volatile("cp.async.wait_group %0;" :: "n"(N) : "memory");
}
__device__ __forceinline__ uint32_t lds32(uint32_t a) {
    uint32_t v;
    asm volatile("ld.shared.b32 %0, [%1];" : "=r"(v) : "r"(a));
    return v;
}
// ldmatrix x4: four 8x8 b16 tiles, frag-ordered
__device__ __forceinline__ void ldsm4(uint32_t* r, uint32_t a) {
    asm volatile("ldmatrix.sync.aligned.m8n8.x4.shared.b16 {%0,%1,%2,%3}, [%4];"
        : "=r"(r[0]), "=r"(r[1]), "=r"(r[2]), "=r"(r[3]) : "r"(a));
}
// mma.sync m16n8k16 row.col bf16 -> f32
__device__ __forceinline__ void mma16816(float* d, const uint32_t* a, const uint32_t* b) {
    asm volatile(
        "mma.sync.aligned.m16n8k16.row.col.f32.bf16.bf16.f32 "
        "{%0,%1,%2,%3}, {%4,%5,%6,%7}, {%8,%9}, {%0,%1,%2,%3};"
        : "+f"(d[0]), "+f"(d[1]), "+f"(d[2]), "+f"(d[3])
        : "r"(a[0]), "r"(a[1]), "r"(a[2]), "r"(a[3]), "r"(b[0]), "r"(b[1]));
}
__device__ __forceinline__ float ex2f(float x) {
    float y; asm("ex2.approx.f32 %0, %1;" : "=f"(y) : "f"(x)); return y;
}
// pack two f32 -> bf16x2 (second operand lands in the LOW half)
__device__ __forceinline__ uint32_t cvt_bf16x2(float hi, float lo) {
    uint32_t r;
    asm("cvt.rn.bf16x2.f32 %0, %1, %2;" : "=r"(r) : "f"(hi), "f"(lo));
    return r;
}
// split two fp32 into bf16x2 hi-word + bf16x2 residual-word
__device__ __forceinline__ void split2(float v0, float v1, uint32_t& hw, uint32_t& lw) {
    hw = cvt_bf16x2(v1, v0);
    float f0 = __uint_as_float(hw << 16);
    float f1 = __uint_as_float(hw & 0xffff0000u);
    lw = cvt_bf16x2(v1 - f1, v0 - f0);
}

// ---------------- scratch (allocation-free rule: device globals) --------
__device__ float g_qkv[(size_t)16384 * 3072];          // fp32 (v cols used)
__device__ __nv_bfloat16 g_xhi[(size_t)16384 * 1024];
__device__ __nv_bfloat16 g_xlo[(size_t)16384 * 1024];
__device__ __nv_bfloat16 g_whi[(size_t)3072 * 1024];   // W_qkv^T split
__device__ __nv_bfloat16 g_wlo[(size_t)3072 * 1024];
__device__ __nv_bfloat16 g_ahi[(size_t)16384 * 1024];  // attention out split
__device__ __nv_bfloat16 g_alo[(size_t)16384 * 1024];
__device__ __nv_bfloat16 g_ohi[(size_t)1024 * 1024];   // W_out^T split
__device__ __nv_bfloat16 g_olo[(size_t)1024 * 1024];
__device__ __nv_bfloat16 g_qhi[(size_t)16384 * 1024];  // scaled by 0.125*log2e
__device__ __nv_bfloat16 g_qlo[(size_t)16384 * 1024];
__device__ __nv_bfloat16 g_khi[(size_t)16384 * 1024];
__device__ __nv_bfloat16 g_klo[(size_t)16384 * 1024];
__device__ __nv_bfloat16 g_vthi[(size_t)2 * 16 * 64 * 8192];  // [b][h][d][s]
__device__ __nv_bfloat16 g_vtlo[(size_t)2 * 16 * 64 * 8192];

// ===================== conversion kernels =====================
__global__ void __launch_bounds__(256)
split_kernel(const float* __restrict__ src, __nv_bfloat16* __restrict__ hi,
             __nv_bfloat16* __restrict__ lo)
{
    size_t i = ((size_t)blockIdx.x * 256 + threadIdx.x) * 4;
    float4 v = *(const float4*)(src + i);
    uint32_t h0, l0w, h1, l1w;
    split2(v.x, v.y, h0, l0w);
    split2(v.z, v.w, h1, l1w);
    ((uint32_t*)(hi + i))[0] = h0; ((uint32_t*)(hi + i))[1] = h1;
    ((uint32_t*)(lo + i))[0] = l0w; ((uint32_t*)(lo + i))[1] = l1w;
}

// W [K,N] fp32 -> W^T [N,K] bf16 hi/lo
__global__ void __launch_bounds__(256)
transpose_split_kernel(const float* __restrict__ W, __nv_bfloat16* __restrict__ hiT,
                       __nv_bfloat16* __restrict__ loT, int K, int N)
{
    __shared__ float t[32][33];
    int n0 = blockIdx.x * 32, k0 = blockIdx.y * 32;
    int tx = threadIdx.x, ty = threadIdx.y;
    #pragma unroll
    for (int i = 0; i < 4; i++)
        t[ty + 8 * i][tx] = W[(size_t)(k0 + ty + 8 * i) * N + n0 + tx];
    __syncthreads();
    #pragma unroll
    for (int i = 0; i < 4; i++) {
        float v = t[tx][ty + 8 * i];
        __nv_bfloat16 h = __float2bfloat16(v);
        size_t o = (size_t)(n0 + ty + 8 * i) * K + k0 + tx;
        hiT[o] = h;
        loT[o] = __float2bfloat16(v - __bfloat162float(h));
    }
}

// v columns of qkv -> per-head transpose [b][h][d][s], split bf16
__global__ void __launch_bounds__(256)
v_transpose_split_kernel(const float* __restrict__ qkv,
                         __nv_bfloat16* __restrict__ vthi,
                         __nv_bfloat16* __restrict__ vtlo)
{
    __shared__ float tbuf[32][33];
    int bh = blockIdx.z;
    int b = bh >> 4, h = bh & 15;
    int s0 = blockIdx.x * 32, d0 = blockIdx.y * 32;
    int tx = threadIdx.x, ty = threadIdx.y;   // 32 x 8
    #pragma unroll
    for (int i = 0; i < 4; i++)
        tbuf[ty + 8 * i][tx] =
            qkv[((size_t)b * 8192 + s0 + ty + 8 * i) * 3072 + 2048 + h * 64 + d0 + tx];
    __syncthreads();
    #pragma unroll
    for (int i = 0; i < 4; i++) {
        float v = tbuf[tx][ty + 8 * i];       // s = s0+tx, d = d0+ty+8i
        size_t o = ((size_t)bh * 64 + d0 + ty + 8 * i) * 8192 + s0 + tx;
        __nv_bfloat16 hv = __float2bfloat16(v);
        vthi[o] = hv;
        vtlo[o] = __float2bfloat16(v - __bfloat162float(hv));
    }
}

// ===================== HMMA bf16x3 GEMM (ldmatrix frags) ====================
// 128 threads, 4 warps in 2x2, warp tile 64x64; CTA tile 128x128; k-chunk 32;
// 2-stage pipeline; fragment loads via ldmatrix.x4 (32 LDSM vs 128 LDS).
#define OP_BYTES   10240u
#define STG_BYTES  40960u

__global__ void __launch_bounds__(128)
gemm_hmma_kernel(const __nv_bfloat16* __restrict__ Ahi, const __nv_bfloat16* __restrict__ Alo,
                 const __nv_bfloat16* __restrict__ Bhi, const __nv_bfloat16* __restrict__ Blo,
                 const float* __restrict__ bias, float* __restrict__ C, int N, int mode,
                 __nv_bfloat16* __restrict__ qhi, __nv_bfloat16* __restrict__ qlo,
                 __nv_bfloat16* __restrict__ khi, __nv_bfloat16* __restrict__ klo)
{
    extern __shared__ __align__(16) char dsm[];
    const int tid  = threadIdx.x;
    const int wid  = tid >> 5;
    const int lane = tid & 31;
    const int g    = lane >> 2;
    const int tig  = lane & 3;
    const int wm   = wid & 1;      // 2 warps along M (64 rows each)
    const int wn   = wid >> 1;     // 2 warps along N (64 cols each)
    const int m0 = blockIdx.y * 128;
    const int n0 = blockIdx.x * 128;

    const uint32_t sbase = smem_u32(dsm);

    // ldmatrix lane-constant address bases (80-byte rows)
    // A: g2=0 rows0-7@k0, g2=1 rows8-15@k0, g2=2 rows0-7@+16B, g2=3 rows8-15@+16B
    const uint32_t baseA = (uint32_t)(((lane & 7) + ((lane >> 3) & 1) * 8) * 80
                                      + ((lane >> 4) & 1) * 16);
    // B: g2=0 n0-7@k0, g2=1 n0-7@+16B, g2=2 n8-15@k0, g2=3 n8-15@+16B
    const uint32_t baseB = (uint32_t)(((lane & 7) + ((lane >> 4) & 1) * 8) * 80
                                      + ((lane >> 3) & 1) * 16);

    // load slots: per operand 512 (row,unit) 16B slots; 4 per thread
    int rowi[4], uni[4];
    #pragma unroll
    for (int i = 0; i < 4; i++) {
        int lin = tid + 128 * i;
        rowi[i] = lin >> 2;
        uni[i]  = lin & 3;
    }

    auto load_chunk = [&](int c) {
        uint32_t sb = sbase + (uint32_t)(c & 1) * STG_BYTES;
        int kof = c * 32;
        #pragma unroll
        for (int i = 0; i < 4; i++) {
            int r = rowi[i], u = uni[i];
            uint32_t so = (uint32_t)(r * 80 + u * 16);
            size_t ga = (size_t)(m0 + r) * 1024 + kof + u * 8;
            size_t gb = (size_t)(n0 + r) * 1024 + kof + u * 8;
            cp_async16(sb + so,                 Ahi + ga);
            cp_async16(sb + OP_BYTES + so,      Alo + ga);
            cp_async16(sb + 2 * OP_BYTES + so,  Bhi + gb);
            cp_async16(sb + 3 * OP_BYTES + so,  Blo + gb);
        }
        CP_COMMIT();
    };

    load_chunk(0); load_chunk(1);

    float acc[4][8][4];
    #pragma unroll
    for (int mt = 0; mt < 4; mt++)
        #pragma unroll
        for (int nt = 0; nt < 8; nt++)
            #pragma unroll
            for (int r = 0; r < 4; r++) acc[mt][nt][r] = 0.f;

    #pragma unroll 1
    for (int c = 0; c < 32; c++) {
        if (c < 31) cp_wait<1>();
        else        cp_wait<0>();
        __syncthreads();

        uint32_t sb = sbase + (uint32_t)(c & 1) * STG_BYTES;
        #pragma unroll
        for (int kh = 0; kh < 2; kh++) {
            const uint32_t kbo = (uint32_t)(kh * 32);
            uint32_t ah[4][4], al[4][4];
            #pragma unroll
            for (int mt = 0; mt < 4; mt++) {
                uint32_t aa = sb + (uint32_t)((wm * 64 + mt * 16) * 80) + baseA + kbo;
                ldsm4(ah[mt], aa);
                ldsm4(al[mt], aa + OP_BYTES);
            }
            #pragma unroll
            for (int nh = 0; nh < 2; nh++) {
                uint32_t bhf[2][4], blf[2][4];   // ntp pair: {b0(2p),b1(2p),b0(2p+1),b1(2p+1)}
                #pragma unroll
                for (int p = 0; p < 2; p++) {
                    int ntp = nh * 2 + p;
                    uint32_t ba = sb + 2 * OP_BYTES +
                                  (uint32_t)((wn * 64 + ntp * 16) * 80) + baseB + kbo;
                    ldsm4(bhf[p], ba);
                    ldsm4(blf[p], ba + OP_BYTES);
                }
                #pragma unroll
                for (int mt = 0; mt < 4; mt++)
                    #pragma unroll
                    for (int p = 0; p < 2; p++) {
                        mma16816(acc[mt][nh * 4 + 2 * p],     ah[mt], &bhf[p][0]);
                        mma16816(acc[mt][nh * 4 + 2 * p + 1], ah[mt], &bhf[p][2]);
                    }
                #pragma unroll
                for (int mt = 0; mt < 4; mt++)
                    #pragma unroll
                    for (int p = 0; p < 2; p++) {
                        mma16816(acc[mt][nh * 4 + 2 * p],     ah[mt], &blf[p][0]);
                        mma16816(acc[mt][nh * 4 + 2 * p + 1], ah[mt], &blf[p][2]);
                    }
                #pragma unroll
                for (int mt = 0; mt < 4; mt++)
                    #pragma unroll
                    for (int p = 0; p < 2; p++) {
                        mma16816(acc[mt][nh * 4 + 2 * p],     al[mt], &bhf[p][0]);
                        mma16816(acc[mt][nh * 4 + 2 * p + 1], al[mt], &bhf[p][2]);
                    }
            }
        }
        __syncthreads();
        if (c < 30) load_chunk(c + 2);
    }

    const float qsc = 0.18033688011112042f;   // (1/8)*log2(e)
    #pragma unroll
    for (int mt = 0; mt < 4; mt++) {
        int row = m0 + wm * 64 + mt * 16 + g;
        #pragma unroll
        for (int nt = 0; nt < 8; nt++) {
            int col = n0 + wn * 64 + nt * 8 + tig * 2;
            float b0 = bias[col], b1 = bias[col + 1];
            float v00 = acc[mt][nt][0] + b0, v01 = acc[mt][nt][1] + b1;
            float v10 = acc[mt][nt][2] + b0, v11 = acc[mt][nt][3] + b1;
            if (mode == 1 && col < 2048) {
                bool isq = col < 1024;
                float s = isq ? qsc : 1.f;
                __nv_bfloat16* hp = isq ? qhi : khi;
                __nv_bfloat16* lp = isq ? qlo : klo;
                int cc = col & 1023;
                uint32_t hw, lw;
                split2(v00 * s, v01 * s, hw, lw);
                *(uint32_t*)&hp[(size_t)row * 1024 + cc] = hw;
                *(uint32_t*)&lp[(size_t)row * 1024 + cc] = lw;
                split2(v10 * s, v11 * s, hw, lw);
                *(uint32_t*)&hp[(size_t)(row + 8) * 1024 + cc] = hw;
                *(uint32_t*)&lp[(size_t)(row + 8) * 1024 + cc] = lw;
            } else {
                *(float2*)&C[(size_t)row * N + col]       = make_float2(v00, v01);
                *(float2*)&C[(size_t)(row + 8) * N + col] = make_float2(v10, v11);
            }
        }
    }
}

// ===================== HMMA blocked ring attention =====================
// grid 2048 = (qt:4, blk:16, h:16, b:2); 256 threads (8 warps x 16 q-rows = 128).
__global__ void __launch_bounds__(256)
attn_hmma_kernel(const __nv_bfloat16* __restrict__ Qhi_g, const __nv_bfloat16* __restrict__ Qlo_g,
                 const __nv_bfloat16* __restrict__ Khi_g, const __nv_bfloat16* __restrict__ Klo_g,
                 const __nv_bfloat16* __restrict__ Vthi_g, const __nv_bfloat16* __restrict__ Vtlo_g,
                 __nv_bfloat16* __restrict__ Ahi_o, __nv_bfloat16* __restrict__ Alo_o)
{
    extern __shared__ __align__(16) char dsm[];
    const int tid  = threadIdx.x;
    const int w    = tid >> 5;
    const int lane = tid & 31;
    const int g    = lane >> 2;
    const int t    = lane & 3;

    const int cta = blockIdx.x;
    const int qt  = cta & 3;
    const int blk = (cta >> 2) & 15;
    const int h   = (cta >> 6) & 15;
    const int b   = cta >> 10;
    const size_t rowbase = (size_t)b * 8192;
    const int s0 = blk * 512 + qt * 128;
    const int bh = b * 16 + h;

    // smem: Qhi[128x144] Qlo(+18432); K 2 stages x (hi 9216 + lo 9216); V same
    const uint32_t sQ = smem_u32(dsm);
    const uint32_t sK = sQ + 36864;
    const uint32_t sV = sQ + 73728;

    // ---- Q load: 256 threads x (1 row-half) of 128 rows ----
    {
        const int lr = tid >> 1, lh = tid & 1;
        const __nv_bfloat16* qh = Qhi_g + (rowbase + s0 + lr) * 1024 + h * 64 + lh * 32;
        const __nv_bfloat16* ql = Qlo_g + (rowbase + s0 + lr) * 1024 + h * 64 + lh * 32;
        uint32_t d = sQ + lr * 144 + lh * 64;
        #pragma unroll
        for (int j = 0; j < 4; j++) {
            cp_async16(d + j * 16,         qh + j * 8);
            cp_async16(d + 18432 + j * 16, ql + j * 8);
        }
    }
    auto load_kv = [&](int c) {
        int stage = c & 1;
        int kb2   = (c >= 8) ? ((blk + 1) & 15) : blk;
        int sk    = kb2 * 512 + (c & 7) * 64;
        const int lr = tid >> 2, qtr = tid & 3;   // 64 rows x 4 quarters
        const __nv_bfloat16* kh = Khi_g + (rowbase + sk + lr) * 1024 + h * 64 + qtr * 16;
        const __nv_bfloat16* kl = Klo_g + (rowbase + sk + lr) * 1024 + h * 64 + qtr * 16;
        uint32_t kd = sK + stage * 18432 + lr * 144 + qtr * 32;
        cp_async16(kd,          kh);
        cp_async16(kd + 16,     kh + 8);
        cp_async16(kd + 9216,      kl);
        cp_async16(kd + 9216 + 16, kl + 8);
        const __nv_bfloat16* vh = Vthi_g + ((size_t)bh * 64 + lr) * 8192 + sk + qtr * 16;
        const __nv_bfloat16* vl = Vtlo_g + ((size_t)bh * 64 + lr) * 8192 + sk + qtr * 16;
        uint32_t vd = sV + stage * 18432 + lr * 144 + qtr * 32;
        cp_async16(vd,          vh);
        cp_async16(vd + 16,     vh + 8);
        cp_async16(vd + 9216,      vl);
        cp_async16(vd + 9216 + 16, vl + 8);
        CP_COMMIT();
    };
    load_kv(0);
    load_kv(1);

    float m0 = -1e30f, m1 = -1e30f, l0 = 0.f, l1 = 0.f;
    float oacc[8][4], ofin[8][4];
    #pragma unroll
    for (int nt = 0; nt < 8; nt++)
        #pragma unroll
        for (int j = 0; j < 4; j++) { oacc[nt][j] = 0.f; ofin[nt][j] = 0.f; }

    #pragma unroll 1
    for (int c = 0; c < 16; c++) {
        cp_wait<1>();
        __syncthreads();
        const uint32_t kb = sK + (c & 1) * 18432;
        const uint32_t vb = sV + (c & 1) * 18432;

        // ---- S = Q K^T (m16 x n64, k=64, bf16x3) ----
        float sacc[8][4];
        #pragma unroll
        for (int nt = 0; nt < 8; nt++)
            #pragma unroll
            for (int j = 0; j < 4; j++) sacc[nt][j] = 0.f;

        #pragma unroll
        for (int ks = 0; ks < 4; ks++) {
            uint32_t qa = sQ + (uint32_t)((w * 16 + g) * 144) + ks * 32 + t * 4;
            uint32_t ah[4], al[4];
            ah[0] = lds32(qa);        ah[1] = lds32(qa + 8 * 144);
            ah[2] = lds32(qa + 16);   ah[3] = lds32(qa + 8 * 144 + 16);
            al[0] = lds32(qa + 18432);           al[1] = lds32(qa + 18432 + 8 * 144);
            al[2] = lds32(qa + 18432 + 16);      al[3] = lds32(qa + 18432 + 8 * 144 + 16);
            uint32_t kf[8][2], klf[8][2];
            #pragma unroll
            for (int nt = 0; nt < 8; nt++) {
                uint32_t ka = kb + (uint32_t)((nt * 8 + g) * 144) + ks * 32 + t * 4;
                kf[nt][0]  = lds32(ka);        kf[nt][1]  = lds32(ka + 16);
                klf[nt][0] = lds32(ka + 9216); klf[nt][1] = lds32(ka + 9216 + 16);
            }
            #pragma unroll
            for (int nt = 0; nt < 8; nt++) mma16816(sacc[nt], ah, kf[nt]);
            #pragma unroll
            for (int nt = 0; nt < 8; nt++) mma16816(sacc[nt], ah, klf[nt]);
            #pragma unroll
            for (int nt = 0; nt < 8; nt++) mma16816(sacc[nt], al, kf[nt]);
        }

        // ---- online softmax in exp2 domain ----
        float mx0 = -1e30f, mx1 = -1e30f;
        #pragma unroll
        for (int nt = 0; nt < 8; nt++) {
            mx0 = fmaxf(mx0, fmaxf(sacc[nt][0], sacc[nt][1]));
            mx1 = fmaxf(mx1, fmaxf(sacc[nt][2], sacc[nt][3]));
        }
        mx0 = fmaxf(mx0, __shfl_xor_sync(0xffffffffu, mx0, 1));
        mx0 = fmaxf(mx0, __shfl_xor_sync(0xffffffffu, mx0, 2));
        mx1 = fmaxf(mx1, __shfl_xor_sync(0xffffffffu, mx1, 1));
        mx1 = fmaxf(mx1, __shfl_xor_sync(0xffffffffu, mx1, 2));
        float mn0 = fmaxf(m0, mx0), mn1 = fmaxf(m1, mx1);
        float alpha0 = ex2f(m0 - mn0), alpha1 = ex2f(m1 - mn1);
        float rs0 = 0.f, rs1 = 0.f;
        #pragma unroll
        for (int nt = 0; nt < 8; nt++) {
            sacc[nt][0] = ex2f(sacc[nt][0] - mn0);
            sacc[nt][1] = ex2f(sacc[nt][1] - mn0);
            sacc[nt][2] = ex2f(sacc[nt][2] - mn1);
            sacc[nt][3] = ex2f(sacc[nt][3] - mn1);
            rs0 += sacc[nt][0] + sacc[nt][1];
            rs1 += sacc[nt][2] + sacc[nt][3];
        }
        rs0 += __shfl_xor_sync(0xffffffffu, rs0, 1);
        rs0 += __shfl_xor_sync(0xffffffffu, rs0, 2);
        rs1 += __shfl_xor_sync(0xffffffffu, rs1, 1);
        rs1 += __shfl_xor_sync(0xffffffffu, rs1, 2);
        l0 = l0 * alpha0 + rs0;
        l1 = l1 * alpha1 + rs1;
        m0 = mn0; m1 = mn1;
        #pragma unroll
        for (int nt = 0; nt < 8; nt++) {
            oacc[nt][0] *= alpha0; oacc[nt][1] *= alpha0;
            oacc[nt][2] *= alpha1; oacc[nt][3] *= alpha1;
        }

        // ---- O += P V (P hi/lo built in registers) ----
        #pragma unroll
        for (int ks = 0; ks < 4; ks++) {
            uint32_t pA[4], pL[4];
            #pragma unroll
            for (int half = 0; half < 2; half++) {
                const float* s2 = sacc[2 * ks + half];
                uint32_t h01, l01, h23, l23;
                split2(s2[0], s2[1], h01, l01);
                split2(s2[2], s2[3], h23, l23);
                pA[2 * half]     = h01;
                pA[2 * half + 1] = h23;
                pL[2 * half]     = l01;
                pL[2 * half + 1] = l23;
            }
            uint32_t vf[8][2], vlf[8][2];
            #pragma unroll
            for (int nt = 0; nt < 8; nt++) {
                uint32_t va = vb + (uint32_t)((nt * 8 + g) * 144) + ks * 32 + t * 4;
                vf[nt][0]  = lds32(va);        vf[nt][1]  = lds32(va + 16);
                vlf[nt][0] = lds32(va + 9216); vlf[nt][1] = lds32(va + 9216 + 16);
            }
            #pragma unroll
            for (int nt = 0; nt < 8; nt++) mma16816(oacc[nt], pA, vf[nt]);
            #pragma unroll
            for (int nt = 0; nt < 8; nt++) mma16816(oacc[nt], pA, vlf[nt]);
            #pragma unroll
            for (int nt = 0; nt < 8; nt++) mma16816(oacc[nt], pL, vf[nt]);
        }

        __syncthreads();
        if (c < 14) load_kv(c + 2);

        if ((c & 7) == 7) {
            float i0 = 1.0f / l0, i1 = 1.0f / l1;
            #pragma unroll
            for (int nt = 0; nt < 8; nt++) {
                ofin[nt][0] += oacc[nt][0] * i0;
                ofin[nt][1] += oacc[nt][1] * i0;
                ofin[nt][2] += oacc[nt][2] * i1;
                ofin[nt][3] += oacc[nt][3] * i1;
                oacc[nt][0] = oacc[nt][1] = oacc[nt][2] = oacc[nt][3] = 0.f;
            }
            m0 = m1 = -1e30f;
            l0 = l1 = 0.f;
        }
    }

    // ---- store O as bf16 hi/lo (feeds gemm2 directly) ----
    size_t r0 = rowbase + s0 + w * 16 + g;
    #pragma unroll
    for (int nt = 0; nt < 8; nt++) {
        int col = h * 64 + nt * 8 + t * 2;
        uint32_t hw, lw;
        split2(ofin[nt][0], ofin[nt][1], hw, lw);
        *(uint32_t*)&Ahi_o[r0 * 1024 + col] = hw;
        *(uint32_t*)&Alo_o[r0 * 1024 + col] = lw;
        split2(ofin[nt][2], ofin[nt][3], hw, lw);
        *(uint32_t*)&Ahi_o[(r0 + 8) * 1024 + col] = hw;
        *(uint32_t*)&Alo_o[(r0 + 8) * 1024 + col] = lw;
    }
}

// ============================ launcher ===================================
extern "C" void kernel_launch(void* const* d_in, const int* in_sizes, int n_in,
                              void* d_out, int out_size)
{
    const float* x    = (const float*)d_in[0];
    const float* Wqkv = (const float*)d_in[1];
    const float* bqkv = (const float*)d_in[2];
    const float* Wout = (const float*)d_in[3];
    const float* bout = (const float*)d_in[4];
    float* out = (float*)d_out;

    float* qkv; cudaGetSymbolAddress((void**)&qkv, g_qkv);
    __nv_bfloat16 *xhi, *xlo, *whi, *wlo, *ahi, *alo, *ohi, *olo;
    __nv_bfloat16 *qhi, *qlo, *khi, *klo, *vthi, *vtlo;
    cudaGetSymbolAddress((void**)&xhi, g_xhi);  cudaGetSymbolAddress((void**)&xlo, g_xlo);
    cudaGetSymbolAddress((void**)&whi, g_whi);  cudaGetSymbolAddress((void**)&wlo, g_wlo);
    cudaGetSymbolAddress((void**)&ahi, g_ahi);  cudaGetSymbolAddress((void**)&alo, g_alo);
    cudaGetSymbolAddress((void**)&ohi, g_ohi);  cudaGetSymbolAddress((void**)&olo, g_olo);
    cudaGetSymbolAddress((void**)&qhi, g_qhi);  cudaGetSymbolAddress((void**)&qlo, g_qlo);
    cudaGetSymbolAddress((void**)&khi, g_khi);  cudaGetSymbolAddress((void**)&klo, g_klo);
    cudaGetSymbolAddress((void**)&vthi, g_vthi); cudaGetSymbolAddress((void**)&vtlo, g_vtlo);

    const int gemm_smem = 2 * 40960;   // 81920 B -> 2 CTAs/SM
    cudaFuncSetAttribute(gemm_hmma_kernel, cudaFuncAttributeMaxDynamicSharedMemorySize,
                         gemm_smem);
    const int attn_smem = 110592;
    cudaFuncSetAttribute(attn_hmma_kernel, cudaFuncAttributeMaxDynamicSharedMemorySize,
                         attn_smem);

    // 0) operand conversion for gemm1
    split_kernel<<<16384, 256>>>(x, xhi, xlo);
    transpose_split_kernel<<<dim3(3072 / 32, 1024 / 32), dim3(32, 8)>>>(
        Wqkv, whi, wlo, 1024, 3072);
    transpose_split_kernel<<<dim3(1024 / 32, 1024 / 32), dim3(32, 8)>>>(
        Wout, ohi, olo, 1024, 1024);

    // 1) qkv = x @ W_qkv + b_qkv; q/k emitted as bf16 hi/lo, v as fp32
    gemm_hmma_kernel<<<dim3(3072 / 128, 16384 / 128), 128, gemm_smem>>>(
        xhi, xlo, whi, wlo, bqkv, qkv, 3072, 1, qhi, qlo, khi, klo);

    // 2) v transpose/split
    v_transpose_split_kernel<<<dim3(256, 2, 32), dim3(32, 8)>>>(qkv, vthi, vtlo);

    // 3) blocked ring attention (HMMA) -> ahi/alo
    attn_hmma_kernel<<<2048, 256, attn_smem>>>(qhi, qlo, khi, klo, vthi, vtlo, ahi, alo);

    // 4) out = att @ W_out + b_out
    gemm_hmma_kernel<<<dim3(1024 / 128, 16384 / 128), 128, gemm_smem>>>(
        ahi, alo, ohi, olo, bout, out, 1024, 0, nullptr, nullptr, nullptr, nullptr);
}

// round 9
// speedup vs baseline: 2.3171x; 1.0016x over previous
#include <cuda_runtime.h>
#include <cuda_bf16.h>
#include <cstdint>

typedef unsigned long long ull;

// ===================== PTX helpers (baseline, compute_103-safe) ==========
__device__ __forceinline__ uint32_t smem_u32(const void* p) {
    uint32_t a;
    asm("{ .reg .u64 t; cvta.to.shared.u64 t, %1; cvt.u32.u64 %0, t; }"
        : "=r"(a) : "l"(p));
    return a;
}
__device__ __forceinline__ void cp_async16(uint32_t dst, const void* src) {
    asm volatile("cp.async.cg.shared.global [%0], [%1], 16;" :: "r"(dst), "l"(src));
}
#define CP_COMMIT() asm volatile("cp.async.commit_group;" ::: "memory")
template <int N>
__device__ __forceinline__ void cp_wait() {
    asm volatile("cp.async.wait_group %0;" :: "n"(N) : "memory");
}
// ldmatrix x4: four 8x8 b16 tiles, frag-ordered
__device__ __forceinline__ void ldsm4(uint32_t* r, uint32_t a) {
    asm volatile("ldmatrix.sync.aligned.m8n8.x4.shared.b16 {%0,%1,%2,%3}, [%4];"
        : "=r"(r[0]), "=r"(r[1]), "=r"(r[2]), "=r"(r[3]) : "r"(a));
}
// mma.sync m16n8k16 row.col bf16 -> f32
__device__ __forceinline__ void mma16816(float* d, const uint32_t* a, const uint32_t* b) {
    asm volatile(
        "mma.sync.aligned.m16n8k16.row.col.f32.bf16.bf16.f32 "
        "{%0,%1,%2,%3}, {%4,%5,%6,%7}, {%8,%9}, {%0,%1,%2,%3};"
        : "+f"(d[0]), "+f"(d[1]), "+f"(d[2]), "+f"(d[3])
        : "r"(a[0]), "r"(a[1]), "r"(a[2]), "r"(a[3]), "r"(b[0]), "r"(b[1]));
}
__device__ __forceinline__ float ex2f(float x) {
    float y; asm("ex2.approx.f32 %0, %1;" : "=f"(y) : "f"(x)); return y;
}
// pack two f32 -> bf16x2 (second operand lands in the LOW half)
__device__ __forceinline__ uint32_t cvt_bf16x2(float hi, float lo) {
    uint32_t r;
    asm("cvt.rn.bf16x2.f32 %0, %1, %2;" : "=r"(r) : "f"(hi), "f"(lo));
    return r;
}
// split two fp32 into bf16x2 hi-word + bf16x2 residual-word
__device__ __forceinline__ void split2(float v0, float v1, uint32_t& hw, uint32_t& lw) {
    hw = cvt_bf16x2(v1, v0);
    float f0 = __uint_as_float(hw << 16);
    float f1 = __uint_as_float(hw & 0xffff0000u);
    lw = cvt_bf16x2(v1 - f1, v0 - f0);
}

// ---------------- scratch (allocation-free rule: device globals) --------
__device__ float g_qkv[(size_t)16384 * 3072];          // fp32 (v cols used)
__device__ __nv_bfloat16 g_xhi[(size_t)16384 * 1024];
__device__ __nv_bfloat16 g_xlo[(size_t)16384 * 1024];
__device__ __nv_bfloat16 g_whi[(size_t)3072 * 1024];   // W_qkv^T split
__device__ __nv_bfloat16 g_wlo[(size_t)3072 * 1024];
__device__ __nv_bfloat16 g_ahi[(size_t)16384 * 1024];  // attention out split
__device__ __nv_bfloat16 g_alo[(size_t)16384 * 1024];
__device__ __nv_bfloat16 g_ohi[(size_t)1024 * 1024];   // W_out^T split
__device__ __nv_bfloat16 g_olo[(size_t)1024 * 1024];
__device__ __nv_bfloat16 g_qhi[(size_t)16384 * 1024];  // scaled by 0.125*log2e
__device__ __nv_bfloat16 g_qlo[(size_t)16384 * 1024];
__device__ __nv_bfloat16 g_khi[(size_t)16384 * 1024];
__device__ __nv_bfloat16 g_klo[(size_t)16384 * 1024];
__device__ __nv_bfloat16 g_vthi[(size_t)2 * 16 * 64 * 8192];  // [b][h][d][s]
__device__ __nv_bfloat16 g_vtlo[(size_t)2 * 16 * 64 * 8192];

// ===================== conversion kernels =====================
__global__ void __launch_bounds__(256)
split_kernel(const float* __restrict__ src, __nv_bfloat16* __restrict__ hi,
             __nv_bfloat16* __restrict__ lo)
{
    size_t i = ((size_t)blockIdx.x * 256 + threadIdx.x) * 4;
    float4 v = *(const float4*)(src + i);
    uint32_t h0, l0w, h1, l1w;
    split2(v.x, v.y, h0, l0w);
    split2(v.z, v.w, h1, l1w);
    ((uint32_t*)(hi + i))[0] = h0; ((uint32_t*)(hi + i))[1] = h1;
    ((uint32_t*)(lo + i))[0] = l0w; ((uint32_t*)(lo + i))[1] = l1w;
}

// W [K,N] fp32 -> W^T [N,K] bf16 hi/lo
__global__ void __launch_bounds__(256)
transpose_split_kernel(const float* __restrict__ W, __nv_bfloat16* __restrict__ hiT,
                       __nv_bfloat16* __restrict__ loT, int K, int N)
{
    __shared__ float t[32][33];
    int n0 = blockIdx.x * 32, k0 = blockIdx.y * 32;
    int tx = threadIdx.x, ty = threadIdx.y;
    #pragma unroll
    for (int i = 0; i < 4; i++)
        t[ty + 8 * i][tx] = W[(size_t)(k0 + ty + 8 * i) * N + n0 + tx];
    __syncthreads();
    #pragma unroll
    for (int i = 0; i < 4; i++) {
        float v = t[tx][ty + 8 * i];
        __nv_bfloat16 h = __float2bfloat16(v);
        size_t o = (size_t)(n0 + ty + 8 * i) * K + k0 + tx;
        hiT[o] = h;
        loT[o] = __float2bfloat16(v - __bfloat162float(h));
    }
}

// v columns of qkv -> per-head transpose [b][h][d][s], split bf16
__global__ void __launch_bounds__(256)
v_transpose_split_kernel(const float* __restrict__ qkv,
                         __nv_bfloat16* __restrict__ vthi,
                         __nv_bfloat16* __restrict__ vtlo)
{
    __shared__ float tbuf[32][33];
    int bh = blockIdx.z;
    int b = bh >> 4, h = bh & 15;
    int s0 = blockIdx.x * 32, d0 = blockIdx.y * 32;
    int tx = threadIdx.x, ty = threadIdx.y;   // 32 x 8
    #pragma unroll
    for (int i = 0; i < 4; i++)
        tbuf[ty + 8 * i][tx] =
            qkv[((size_t)b * 8192 + s0 + ty + 8 * i) * 3072 + 2048 + h * 64 + d0 + tx];
    __syncthreads();
    #pragma unroll
    for (int i = 0; i < 4; i++) {
        float v = tbuf[tx][ty + 8 * i];       // s = s0+tx, d = d0+ty+8i
        size_t o = ((size_t)bh * 64 + d0 + ty + 8 * i) * 8192 + s0 + tx;
        __nv_bfloat16 hv = __float2bfloat16(v);
        vthi[o] = hv;
        vtlo[o] = __float2bfloat16(v - __bfloat162float(hv));
    }
}

// ===================== HMMA bf16x3 GEMM (ldmatrix frags) ====================
// 128 threads, 4 warps in 2x2, warp tile 64x64; CTA tile 128x128; k-chunk 32;
// 2-stage pipeline; fragment loads via ldmatrix.x4.
#define OP_BYTES   10240u
#define STG_BYTES  40960u

__global__ void __launch_bounds__(128)
gemm_hmma_kernel(const __nv_bfloat16* __restrict__ Ahi, const __nv_bfloat16* __restrict__ Alo,
                 const __nv_bfloat16* __restrict__ Bhi, const __nv_bfloat16* __restrict__ Blo,
                 const float* __restrict__ bias, float* __restrict__ C, int N, int mode,
                 __nv_bfloat16* __restrict__ qhi, __nv_bfloat16* __restrict__ qlo,
                 __nv_bfloat16* __restrict__ khi, __nv_bfloat16* __restrict__ klo)
{
    extern __shared__ __align__(16) char dsm[];
    const int tid  = threadIdx.x;
    const int wid  = tid >> 5;
    const int lane = tid & 31;
    const int g    = lane >> 2;
    const int tig  = lane & 3;
    const int wm   = wid & 1;      // 2 warps along M (64 rows each)
    const int wn   = wid >> 1;     // 2 warps along N (64 cols each)
    const int m0 = blockIdx.y * 128;
    const int n0 = blockIdx.x * 128;

    const uint32_t sbase = smem_u32(dsm);

    const uint32_t baseA = (uint32_t)(((lane & 7) + ((lane >> 3) & 1) * 8) * 80
                                      + ((lane >> 4) & 1) * 16);
    const uint32_t baseB = (uint32_t)(((lane & 7) + ((lane >> 4) & 1) * 8) * 80
                                      + ((lane >> 3) & 1) * 16);

    int rowi[4], uni[4];
    #pragma unroll
    for (int i = 0; i < 4; i++) {
        int lin = tid + 128 * i;
        rowi[i] = lin >> 2;
        uni[i]  = lin & 3;
    }

    auto load_chunk = [&](int c) {
        uint32_t sb = sbase + (uint32_t)(c & 1) * STG_BYTES;
        int kof = c * 32;
        #pragma unroll
        for (int i = 0; i < 4; i++) {
            int r = rowi[i], u = uni[i];
            uint32_t so = (uint32_t)(r * 80 + u * 16);
            size_t ga = (size_t)(m0 + r) * 1024 + kof + u * 8;
            size_t gb = (size_t)(n0 + r) * 1024 + kof + u * 8;
            cp_async16(sb + so,                 Ahi + ga);
            cp_async16(sb + OP_BYTES + so,      Alo + ga);
            cp_async16(sb + 2 * OP_BYTES + so,  Bhi + gb);
            cp_async16(sb + 3 * OP_BYTES + so,  Blo + gb);
        }
        CP_COMMIT();
    };

    load_chunk(0); load_chunk(1);

    float acc[4][8][4];
    #pragma unroll
    for (int mt = 0; mt < 4; mt++)
        #pragma unroll
        for (int nt = 0; nt < 8; nt++)
            #pragma unroll
            for (int r = 0; r < 4; r++) acc[mt][nt][r] = 0.f;

    #pragma unroll 1
    for (int c = 0; c < 32; c++) {
        if (c < 31) cp_wait<1>();
        else        cp_wait<0>();
        __syncthreads();

        uint32_t sb = sbase + (uint32_t)(c & 1) * STG_BYTES;
        #pragma unroll
        for (int kh = 0; kh < 2; kh++) {
            const uint32_t kbo = (uint32_t)(kh * 32);
            uint32_t ah[4][4], al[4][4];
            #pragma unroll
            for (int mt = 0; mt < 4; mt++) {
                uint32_t aa = sb + (uint32_t)((wm * 64 + mt * 16) * 80) + baseA + kbo;
                ldsm4(ah[mt], aa);
                ldsm4(al[mt], aa + OP_BYTES);
            }
            #pragma unroll
            for (int nh = 0; nh < 2; nh++) {
                uint32_t bhf[2][4], blf[2][4];
                #pragma unroll
                for (int p = 0; p < 2; p++) {
                    int ntp = nh * 2 + p;
                    uint32_t ba = sb + 2 * OP_BYTES +
                                  (uint32_t)((wn * 64 + ntp * 16) * 80) + baseB + kbo;
                    ldsm4(bhf[p], ba);
                    ldsm4(blf[p], ba + OP_BYTES);
                }
                #pragma unroll
                for (int mt = 0; mt < 4; mt++)
                    #pragma unroll
                    for (int p = 0; p < 2; p++) {
                        mma16816(acc[mt][nh * 4 + 2 * p],     ah[mt], &bhf[p][0]);
                        mma16816(acc[mt][nh * 4 + 2 * p + 1], ah[mt], &bhf[p][2]);
                    }
                #pragma unroll
                for (int mt = 0; mt < 4; mt++)
                    #pragma unroll
                    for (int p = 0; p < 2; p++) {
                        mma16816(acc[mt][nh * 4 + 2 * p],     ah[mt], &blf[p][0]);
                        mma16816(acc[mt][nh * 4 + 2 * p + 1], ah[mt], &blf[p][2]);
                    }
                #pragma unroll
                for (int mt = 0; mt < 4; mt++)
                    #pragma unroll
                    for (int p = 0; p < 2; p++) {
                        mma16816(acc[mt][nh * 4 + 2 * p],     al[mt], &bhf[p][0]);
                        mma16816(acc[mt][nh * 4 + 2 * p + 1], al[mt], &bhf[p][2]);
                    }
            }
        }
        __syncthreads();
        if (c < 30) load_chunk(c + 2);
    }

    const float qsc = 0.18033688011112042f;   // (1/8)*log2(e)
    #pragma unroll
    for (int mt = 0; mt < 4; mt++) {
        int row = m0 + wm * 64 + mt * 16 + g;
        #pragma unroll
        for (int nt = 0; nt < 8; nt++) {
            int col = n0 + wn * 64 + nt * 8 + tig * 2;
            float b0 = bias[col], b1 = bias[col + 1];
            float v00 = acc[mt][nt][0] + b0, v01 = acc[mt][nt][1] + b1;
            float v10 = acc[mt][nt][2] + b0, v11 = acc[mt][nt][3] + b1;
            if (mode == 1 && col < 2048) {
                bool isq = col < 1024;
                float s = isq ? qsc : 1.f;
                __nv_bfloat16* hp = isq ? qhi : khi;
                __nv_bfloat16* lp = isq ? qlo : klo;
                int cc = col & 1023;
                uint32_t hw, lw;
                split2(v00 * s, v01 * s, hw, lw);
                *(uint32_t*)&hp[(size_t)row * 1024 + cc] = hw;
                *(uint32_t*)&lp[(size_t)row * 1024 + cc] = lw;
                split2(v10 * s, v11 * s, hw, lw);
                *(uint32_t*)&hp[(size_t)(row + 8) * 1024 + cc] = hw;
                *(uint32_t*)&lp[(size_t)(row + 8) * 1024 + cc] = lw;
            } else {
                *(float2*)&C[(size_t)row * N + col]       = make_float2(v00, v01);
                *(float2*)&C[(size_t)(row + 8) * N + col] = make_float2(v10, v11);
            }
        }
    }
}

// ===================== HMMA blocked ring attention (ldmatrix) ==============
// grid 2048 = (qt:4, blk:16, h:16, b:2); 256 threads (8 warps x 16 q-rows).
__global__ void __launch_bounds__(256)
attn_hmma_kernel(const __nv_bfloat16* __restrict__ Qhi_g, const __nv_bfloat16* __restrict__ Qlo_g,
                 const __nv_bfloat16* __restrict__ Khi_g, const __nv_bfloat16* __restrict__ Klo_g,
                 const __nv_bfloat16* __restrict__ Vthi_g, const __nv_bfloat16* __restrict__ Vtlo_g,
                 __nv_bfloat16* __restrict__ Ahi_o, __nv_bfloat16* __restrict__ Alo_o)
{
    extern __shared__ __align__(16) char dsm[];
    const int tid  = threadIdx.x;
    const int w    = tid >> 5;
    const int lane = tid & 31;
    const int g    = lane >> 2;
    const int t    = lane & 3;

    const int cta = blockIdx.x;
    const int qt  = cta & 3;
    const int blk = (cta >> 2) & 15;
    const int h   = (cta >> 6) & 15;
    const int b   = cta >> 10;
    const size_t rowbase = (size_t)b * 8192;
    const int s0 = blk * 512 + qt * 128;
    const int bh = b * 16 + h;

    // smem: Qhi[128x144] Qlo(+18432); K 2 stages x (hi 9216 + lo 9216); V same
    const uint32_t sQ = smem_u32(dsm);
    const uint32_t sK = sQ + 36864;
    const uint32_t sV = sQ + 73728;

    // ldmatrix lane-constant bases (144-byte rows; 144%128=16 -> conflict-free)
    const uint32_t baseA = (uint32_t)(((lane & 7) + ((lane >> 3) & 1) * 8) * 144
                                      + ((lane >> 4) & 1) * 16);
    const uint32_t baseB = (uint32_t)(((lane & 7) + ((lane >> 4) & 1) * 8) * 144
                                      + ((lane >> 3) & 1) * 16);

    // ---- Q load: 256 threads x (1 row-half) of 128 rows ----
    {
        const int lr = tid >> 1, lh = tid & 1;
        const __nv_bfloat16* qh = Qhi_g + (rowbase + s0 + lr) * 1024 + h * 64 + lh * 32;
        const __nv_bfloat16* ql = Qlo_g + (rowbase + s0 + lr) * 1024 + h * 64 + lh * 32;
        uint32_t d = sQ + lr * 144 + lh * 64;
        #pragma unroll
        for (int j = 0; j < 4; j++) {
            cp_async16(d + j * 16,         qh + j * 8);
            cp_async16(d + 18432 + j * 16, ql + j * 8);
        }
    }
    auto load_kv = [&](int c) {
        int stage = c & 1;
        int kb2   = (c >= 8) ? ((blk + 1) & 15) : blk;
        int sk    = kb2 * 512 + (c & 7) * 64;
        const int lr = tid >> 2, qtr = tid & 3;   // 64 rows x 4 quarters
        const __nv_bfloat16* kh = Khi_g + (rowbase + sk + lr) * 1024 + h * 64 + qtr * 16;
        const __nv_bfloat16* kl = Klo_g + (rowbase + sk + lr) * 1024 + h * 64 + qtr * 16;
        uint32_t kd = sK + stage * 18432 + lr * 144 + qtr * 32;
        cp_async16(kd,          kh);
        cp_async16(kd + 16,     kh + 8);
        cp_async16(kd + 9216,      kl);
        cp_async16(kd + 9216 + 16, kl + 8);
        const __nv_bfloat16* vh = Vthi_g + ((size_t)bh * 64 + lr) * 8192 + sk + qtr * 16;
        const __nv_bfloat16* vl = Vtlo_g + ((size_t)bh * 64 + lr) * 8192 + sk + qtr * 16;
        uint32_t vd = sV + stage * 18432 + lr * 144 + qtr * 32;
        cp_async16(vd,          vh);
        cp_async16(vd + 16,     vh + 8);
        cp_async16(vd + 9216,      vl);
        cp_async16(vd + 9216 + 16, vl + 8);
        CP_COMMIT();
    };
    load_kv(0);
    load_kv(1);

    float m0 = -1e30f, m1 = -1e30f, l0 = 0.f, l1 = 0.f;
    float oacc[8][4], ofin[8][4];
    #pragma unroll
    for (int nt = 0; nt < 8; nt++)
        #pragma unroll
        for (int j = 0; j < 4; j++) { oacc[nt][j] = 0.f; ofin[nt][j] = 0.f; }

    #pragma unroll 1
    for (int c = 0; c < 16; c++) {
        cp_wait<1>();
        __syncthreads();
        const uint32_t kb = sK + (c & 1) * 18432;
        const uint32_t vb = sV + (c & 1) * 18432;

        // ---- S = Q K^T (m16 x n64, k=64, bf16x3), ldmatrix frags ----
        float sacc[8][4];
        #pragma unroll
        for (int nt = 0; nt < 8; nt++)
            #pragma unroll
            for (int j = 0; j < 4; j++) sacc[nt][j] = 0.f;

        #pragma unroll
        for (int ks = 0; ks < 4; ks++) {
            uint32_t qa = sQ + (uint32_t)(w * 16 * 144) + baseA + ks * 32;
            uint32_t ah[4], al[4];
            ldsm4(ah, qa);
            ldsm4(al, qa + 18432);
            #pragma unroll
            for (int p = 0; p < 4; p++) {
                uint32_t ka = kb + (uint32_t)(p * 16 * 144) + baseB + ks * 32;
                uint32_t kh4[4], kl4[4];
                ldsm4(kh4, ka);
                ldsm4(kl4, ka + 9216);
                mma16816(sacc[2 * p],     ah, &kh4[0]);
                mma16816(sacc[2 * p + 1], ah, &kh4[2]);
                mma16816(sacc[2 * p],     ah, &kl4[0]);
                mma16816(sacc[2 * p + 1], ah, &kl4[2]);
                mma16816(sacc[2 * p],     al, &kh4[0]);
                mma16816(sacc[2 * p + 1], al, &kh4[2]);
            }
        }

        // ---- online softmax in exp2 domain ----
        float mx0 = -1e30f, mx1 = -1e30f;
        #pragma unroll
        for (int nt = 0; nt < 8; nt++) {
            mx0 = fmaxf(mx0, fmaxf(sacc[nt][0], sacc[nt][1]));
            mx1 = fmaxf(mx1, fmaxf(sacc[nt][2], sacc[nt][3]));
        }
        mx0 = fmaxf(mx0, __shfl_xor_sync(0xffffffffu, mx0, 1));
        mx0 = fmaxf(mx0, __shfl_xor_sync(0xffffffffu, mx0, 2));
        mx1 = fmaxf(mx1, __shfl_xor_sync(0xffffffffu, mx1, 1));
        mx1 = fmaxf(mx1, __shfl_xor_sync(0xffffffffu, mx1, 2));
        float mn0 = fmaxf(m0, mx0), mn1 = fmaxf(m1, mx1);
        float alpha0 = ex2f(m0 - mn0), alpha1 = ex2f(m1 - mn1);
        float rs0 = 0.f, rs1 = 0.f;
        #pragma unroll
        for (int nt = 0; nt < 8; nt++) {
            sacc[nt][0] = ex2f(sacc[nt][0] - mn0);
            sacc[nt][1] = ex2f(sacc[nt][1] - mn0);
            sacc[nt][2] = ex2f(sacc[nt][2] - mn1);
            sacc[nt][3] = ex2f(sacc[nt][3] - mn1);
            rs0 += sacc[nt][0] + sacc[nt][1];
            rs1 += sacc[nt][2] + sacc[nt][3];
        }
        rs0 += __shfl_xor_sync(0xffffffffu, rs0, 1);
        rs0 += __shfl_xor_sync(0xffffffffu, rs0, 2);
        rs1 += __shfl_xor_sync(0xffffffffu, rs1, 1);
        rs1 += __shfl_xor_sync(0xffffffffu, rs1, 2);
        l0 = l0 * alpha0 + rs0;
        l1 = l1 * alpha1 + rs1;
        m0 = mn0; m1 = mn1;
        #pragma unroll
        for (int nt = 0; nt < 8; nt++) {
            oacc[nt][0] *= alpha0; oacc[nt][1] *= alpha0;
            oacc[nt][2] *= alpha1; oacc[nt][3] *= alpha1;
        }

        // ---- O += P V (P hi/lo built in registers; V frags via ldmatrix) ----
        #pragma unroll
        for (int ks = 0; ks < 4; ks++) {
            uint32_t pA[4], pL[4];
            #pragma unroll
            for (int half = 0; half < 2; half++) {
                const float* s2 = sacc[2 * ks + half];
                uint32_t h01, l01, h23, l23;
                split2(s2[0], s2[1], h01, l01);
                split2(s2[2], s2[3], h23, l23);
                pA[2 * half]     = h01;
                pA[2 * half + 1] = h23;
                pL[2 * half]     = l01;
                pL[2 * half + 1] = l23;
            }
            #pragma unroll
            for (int p = 0; p < 4; p++) {
                uint32_t va = vb + (uint32_t)(p * 16 * 144) + baseB + ks * 32;
                uint32_t vh4[4], vl4[4];
                ldsm4(vh4, va);
                ldsm4(vl4, va + 9216);
                mma16816(oacc[2 * p],     pA, &vh4[0]);
                mma16816(oacc[2 * p + 1], pA, &vh4[2]);
                mma16816(oacc[2 * p],     pA, &vl4[0]);
                mma16816(oacc[2 * p + 1], pA, &vl4[2]);
                mma16816(oacc[2 * p],     pL, &vh4[0]);
                mma16816(oacc[2 * p + 1], pL, &vh4[2]);
            }
        }

        __syncthreads();
        if (c < 14) load_kv(c + 2);

        if ((c & 7) == 7) {
            float i0 = 1.0f / l0, i1 = 1.0f / l1;
            #pragma unroll
            for (int nt = 0; nt < 8; nt++) {
                ofin[nt][0] += oacc[nt][0] * i0;
                ofin[nt][1] += oacc[nt][1] * i0;
                ofin[nt][2] += oacc[nt][2] * i1;
                ofin[nt][3] += oacc[nt][3] * i1;
                oacc[nt][0] = oacc[nt][1] = oacc[nt][2] = oacc[nt][3] = 0.f;
            }
            m0 = m1 = -1e30f;
            l0 = l1 = 0.f;
        }
    }

    // ---- store O as bf16 hi/lo (feeds gemm2 directly) ----
    size_t r0 = rowbase + s0 + w * 16 + g;
    #pragma unroll
    for (int nt = 0; nt < 8; nt++) {
        int col = h * 64 + nt * 8 + t * 2;
        uint32_t hw, lw;
        split2(ofin[nt][0], ofin[nt][1], hw, lw);
        *(uint32_t*)&Ahi_o[r0 * 1024 + col] = hw;
        *(uint32_t*)&Alo_o[r0 * 1024 + col] = lw;
        split2(ofin[nt][2], ofin[nt][3], hw, lw);
        *(uint32_t*)&Ahi_o[(r0 + 8) * 1024 + col] = hw;
        *(uint32_t*)&Alo_o[(r0 + 8) * 1024 + col] = lw;
    }
}

// ============================ launcher ===================================
extern "C" void kernel_launch(void* const* d_in, const int* in_sizes, int n_in,
                              void* d_out, int out_size)
{
    const float* x    = (const float*)d_in[0];
    const float* Wqkv = (const float*)d_in[1];
    const float* bqkv = (const float*)d_in[2];
    const float* Wout = (const float*)d_in[3];
    const float* bout = (const float*)d_in[4];
    float* out = (float*)d_out;

    float* qkv; cudaGetSymbolAddress((void**)&qkv, g_qkv);
    __nv_bfloat16 *xhi, *xlo, *whi, *wlo, *ahi, *alo, *ohi, *olo;
    __nv_bfloat16 *qhi, *qlo, *khi, *klo, *vthi, *vtlo;
    cudaGetSymbolAddress((void**)&xhi, g_xhi);  cudaGetSymbolAddress((void**)&xlo, g_xlo);
    cudaGetSymbolAddress((void**)&whi, g_whi);  cudaGetSymbolAddress((void**)&wlo, g_wlo);
    cudaGetSymbolAddress((void**)&ahi, g_ahi);  cudaGetSymbolAddress((void**)&alo, g_alo);
    cudaGetSymbolAddress((void**)&ohi, g_ohi);  cudaGetSymbolAddress((void**)&olo, g_olo);
    cudaGetSymbolAddress((void**)&qhi, g_qhi);  cudaGetSymbolAddress((void**)&qlo, g_qlo);
    cudaGetSymbolAddress((void**)&khi, g_khi);  cudaGetSymbolAddress((void**)&klo, g_klo);
    cudaGetSymbolAddress((void**)&vthi, g_vthi); cudaGetSymbolAddress((void**)&vtlo, g_vtlo);

    const int gemm_smem = 2 * 40960;   // 81920 B -> 2 CTAs/SM
    cudaFuncSetAttribute(gemm_hmma_kernel, cudaFuncAttributeMaxDynamicSharedMemorySize,
                         gemm_smem);
    const int attn_smem = 110592;
    cudaFuncSetAttribute(attn_hmma_kernel, cudaFuncAttributeMaxDynamicSharedMemorySize,
                         attn_smem);

    // 0) operand conversion for gemm1
    split_kernel<<<16384, 256>>>(x, xhi, xlo);
    transpose_split_kernel<<<dim3(3072 / 32, 1024 / 32), dim3(32, 8)>>>(
        Wqkv, whi, wlo, 1024, 3072);
    transpose_split_kernel<<<dim3(1024 / 32, 1024 / 32), dim3(32, 8)>>>(
        Wout, ohi, olo, 1024, 1024);

    // 1) qkv = x @ W_qkv + b_qkv; q/k emitted as bf16 hi/lo, v as fp32
    gemm_hmma_kernel<<<dim3(3072 / 128, 16384 / 128), 128, gemm_smem>>>(
        xhi, xlo, whi, wlo, bqkv, qkv, 3072, 1, qhi, qlo, khi, klo);

    // 2) v transpose/split
    v_transpose_split_kernel<<<dim3(256, 2, 32), dim3(32, 8)>>>(qkv, vthi, vtlo);

    // 3) blocked ring attention (HMMA, ldmatrix) -> ahi/alo
    attn_hmma_kernel<<<2048, 256, attn_smem>>>(qhi, qlo, khi, klo, vthi, vtlo, ahi, alo);

    // 4) out = att @ W_out + b_out
    gemm_hmma_kernel<<<dim3(1024 / 128, 16384 / 128), 128, gemm_smem>>>(
        ahi, alo, ohi, olo, bout, out, 1024, 0, nullptr, nullptr, nullptr, nullptr);
}